// round 1
// baseline (speedup 1.0000x reference)
#include <cuda_runtime.h>
#include <cuda_bf16.h>

#define Bn 2
#define Sn 2048
#define Dn 1024
#define Hn 16
#define DKn 64

// Scratch: projected Q/K/V in [B,H,S,DK] layout, attention output in [B,S,D]
__device__ float g_Q[(size_t)Bn * Hn * Sn * DKn];
__device__ float g_K[(size_t)Bn * Hn * Sn * DKn];
__device__ float g_V[(size_t)Bn * Hn * Sn * DKn];
__device__ float g_A[(size_t)Bn * Sn * Dn];

// ---------------------------------------------------------------------------
// SGEMM with bias: Y[m,n] = sum_k X[m,k] * W[n,k] + bias[n]
// M=4096, N=K=1024. BM=BN=128, BK=8, 256 threads, 8x8 per-thread tile.
// permute=1: write into [B,H,S,DK] layout (for Q/K/V); else row-major [M,N].
// ---------------------------------------------------------------------------
__global__ __launch_bounds__(256) void sgemm_bias(
    const float* __restrict__ X,
    const float* __restrict__ W,
    const float* __restrict__ bias,
    float* __restrict__ Y,
    int permute)
{
    __shared__ float As[8][128];   // [k][m] (transposed)
    __shared__ float Bs[8][128];   // [k][n] (transposed)

    const int K  = Dn;
    const int m0 = blockIdx.x * 128;
    const int n0 = blockIdx.y * 128;
    const int tid = threadIdx.x;
    const int tn = tid & 15;       // 0..15 -> col group
    const int tm = tid >> 4;       // 0..15 -> row group
    const int lr = tid >> 1;       // 0..127 load row
    const int lh = tid & 1;        // which half of the 8-wide k slab

    const float* Xp = X + (size_t)(m0 + lr) * K + lh * 4;
    const float* Wp = W + (size_t)(n0 + lr) * K + lh * 4;

    float c[8][8];
#pragma unroll
    for (int i = 0; i < 8; i++)
#pragma unroll
        for (int j = 0; j < 8; j++) c[i][j] = 0.f;

    for (int k0 = 0; k0 < K; k0 += 8) {
        float4 av = *(const float4*)(Xp + k0);
        float4 bv = *(const float4*)(Wp + k0);
        As[lh * 4 + 0][lr] = av.x; As[lh * 4 + 1][lr] = av.y;
        As[lh * 4 + 2][lr] = av.z; As[lh * 4 + 3][lr] = av.w;
        Bs[lh * 4 + 0][lr] = bv.x; Bs[lh * 4 + 1][lr] = bv.y;
        Bs[lh * 4 + 2][lr] = bv.z; Bs[lh * 4 + 3][lr] = bv.w;
        __syncthreads();

#pragma unroll
        for (int kk = 0; kk < 8; kk++) {
            float a[8], b[8];
            *(float4*)(a)     = *(const float4*)&As[kk][tm * 8];
            *(float4*)(a + 4) = *(const float4*)&As[kk][tm * 8 + 4];
            *(float4*)(b)     = *(const float4*)&Bs[kk][tn * 8];
            *(float4*)(b + 4) = *(const float4*)&Bs[kk][tn * 8 + 4];
#pragma unroll
            for (int i = 0; i < 8; i++)
#pragma unroll
                for (int j = 0; j < 8; j++)
                    c[i][j] = fmaf(a[i], b[j], c[i][j]);
        }
        __syncthreads();
    }

#pragma unroll
    for (int i = 0; i < 8; i++) {
        const int m = m0 + tm * 8 + i;
#pragma unroll
        for (int j = 0; j < 8; j++) {
            const int n = n0 + tn * 8 + j;
            const float v = c[i][j] + bias[n];
            if (permute) {
                // m = b*S + s ; n = h*DK + dk  ->  [B,H,S,DK]
                const int b = m >> 11;          // /Sn
                const int s = m & (Sn - 1);
                const int h = n >> 6;           // /DKn
                const int dk = n & (DKn - 1);
                Y[(((size_t)(b * Hn + h)) * Sn + s) * DKn + dk] = v;
            } else {
                Y[(size_t)m * Dn + n] = v;
            }
        }
    }
}

// ---------------------------------------------------------------------------
// Causal flash attention. One block per (q-tile of 64 rows, bh in B*H).
// 64x64 KV tiles, online softmax, per-thread 4x4 micro-tiles (16x16 grid).
// Smem: Qs [dk][qrow], KP reused as K[dk][krow] then P[qrow][kcol], Vs [krow][dk]
// ---------------------------------------------------------------------------
__global__ __launch_bounds__(256) void attn_fwd()
{
    __shared__ float Qs[64][64];
    __shared__ float KP[64][64];
    __shared__ float Vs[64][64];

    const int qt  = blockIdx.x;            // 0..31
    const int bh  = blockIdx.y;            // 0..31
    const int tid = threadIdx.x;
    const int tx  = tid & 15;              // kv-col / dk group
    const int ty  = tid >> 4;              // q-row group

    const float* Qg = g_Q + (size_t)bh * Sn * DKn;
    const float* Kg = g_K + (size_t)bh * Sn * DKn;
    const float* Vg = g_V + (size_t)bh * Sn * DKn;
    const int q0 = qt * 64;

    // Load Q tile transposed: Qs[k][row]
    {
        const int row = tid & 63, quad = tid >> 6;
        const float* src = Qg + (size_t)(q0 + row) * DKn + quad * 16;
#pragma unroll
        for (int w = 0; w < 4; w++) {
            float4 v = *(const float4*)(src + w * 4);
            const int k = quad * 16 + w * 4;
            Qs[k + 0][row] = v.x; Qs[k + 1][row] = v.y;
            Qs[k + 2][row] = v.z; Qs[k + 3][row] = v.w;
        }
    }

    float m[4], l[4], o[4][4];
#pragma unroll
    for (int i = 0; i < 4; i++) {
        m[i] = -1e30f; l[i] = 0.f;
#pragma unroll
        for (int j = 0; j < 4; j++) o[i][j] = 0.f;
    }
    __syncthreads();

    for (int kt = 0; kt <= qt; kt++) {
        const int k0 = kt * 64;
        // Load K transposed into KP, V natural into Vs
        {
            const int row = tid & 63, quad = tid >> 6;
            const float* src = Kg + (size_t)(k0 + row) * DKn + quad * 16;
#pragma unroll
            for (int w = 0; w < 4; w++) {
                float4 v = *(const float4*)(src + w * 4);
                const int k = quad * 16 + w * 4;
                KP[k + 0][row] = v.x; KP[k + 1][row] = v.y;
                KP[k + 2][row] = v.z; KP[k + 3][row] = v.w;
            }
#pragma unroll
            for (int w = 0; w < 4; w++) {
                const int off = w * 1024 + tid * 4;
                const int r = off >> 6, cc = off & 63;
                *(float4*)&Vs[r][cc] =
                    *(const float4*)(Vg + (size_t)(k0 + r) * DKn + cc);
            }
        }
        __syncthreads();

        // S = Q K^T
        float s[4][4];
#pragma unroll
        for (int i = 0; i < 4; i++)
#pragma unroll
            for (int j = 0; j < 4; j++) s[i][j] = 0.f;

#pragma unroll
        for (int kk = 0; kk < 64; kk++) {
            float4 a = *(const float4*)&Qs[kk][ty * 4];
            float4 b = *(const float4*)&KP[kk][tx * 4];
            float av[4] = {a.x, a.y, a.z, a.w};
            float bv[4] = {b.x, b.y, b.z, b.w};
#pragma unroll
            for (int i = 0; i < 4; i++)
#pragma unroll
                for (int j = 0; j < 4; j++)
                    s[i][j] = fmaf(av[i], bv[j], s[i][j]);
        }

        const float scale = 0.125f;   // 1/sqrt(DK=64)
        const bool diag = (kt == qt);
#pragma unroll
        for (int i = 0; i < 4; i++) {
            const int qrow = q0 + ty * 4 + i;
#pragma unroll
            for (int j = 0; j < 4; j++) {
                float v = s[i][j] * scale;
                if (diag && (k0 + tx * 4 + j > qrow)) v = -1e30f;
                s[i][j] = v;
            }
        }

        // Online softmax update (row stats shared by the 16 tx-lanes of a row group)
#pragma unroll
        for (int i = 0; i < 4; i++) {
            float rmax = fmaxf(fmaxf(s[i][0], s[i][1]), fmaxf(s[i][2], s[i][3]));
#pragma unroll
            for (int off = 1; off < 16; off <<= 1)
                rmax = fmaxf(rmax, __shfl_xor_sync(0xffffffffu, rmax, off));
            const float mnew  = fmaxf(m[i], rmax);
            const float alpha = __expf(m[i] - mnew);
            float rsum = 0.f;
#pragma unroll
            for (int j = 0; j < 4; j++) {
                const float p = __expf(s[i][j] - mnew);
                s[i][j] = p;
                rsum += p;
            }
#pragma unroll
            for (int off = 1; off < 16; off <<= 1)
                rsum += __shfl_xor_sync(0xffffffffu, rsum, off);
            l[i] = l[i] * alpha + rsum;
            m[i] = mnew;
#pragma unroll
            for (int j = 0; j < 4; j++) o[i][j] *= alpha;
        }

        __syncthreads();   // everyone done reading KP as K
        // Write P into KP: P[qrow][kcol]
#pragma unroll
        for (int i = 0; i < 4; i++)
            *(float4*)&KP[ty * 4 + i][tx * 4] =
                make_float4(s[i][0], s[i][1], s[i][2], s[i][3]);
        __syncthreads();

        // O += P V
#pragma unroll
        for (int kk = 0; kk < 64; kk++) {
            float4 bv = *(const float4*)&Vs[kk][tx * 4];
#pragma unroll
            for (int i = 0; i < 4; i++) {
                const float p = KP[ty * 4 + i][kk];
                o[i][0] = fmaf(p, bv.x, o[i][0]);
                o[i][1] = fmaf(p, bv.y, o[i][1]);
                o[i][2] = fmaf(p, bv.z, o[i][2]);
                o[i][3] = fmaf(p, bv.w, o[i][3]);
            }
        }
        __syncthreads();   // before next tile reuses KP/Vs
    }

    // Finalize and write [B,S,D] with D = h*DK + dk
    const int b = bh >> 4, h = bh & 15;
#pragma unroll
    for (int i = 0; i < 4; i++) {
        const float inv = 1.0f / l[i];
        const int srow = q0 + ty * 4 + i;
        float4 v = make_float4(o[i][0] * inv, o[i][1] * inv,
                               o[i][2] * inv, o[i][3] * inv);
        *(float4*)&g_A[((size_t)(b * Sn + srow)) * Dn + h * DKn + tx * 4] = v;
    }
}

// ---------------------------------------------------------------------------
// Input order (setup_inputs dict order):
// 0:k 1:q 2:v 3:w_q 4:b_q 5:w_k 6:b_k 7:w_v 8:b_v 9:w_o 10:b_o 11:mask
// mask is deterministic causal tril -> applied analytically in attn_fwd.
// ---------------------------------------------------------------------------
extern "C" void kernel_launch(void* const* d_in, const int* in_sizes, int n_in,
                              void* d_out, int out_size)
{
    const float* k_in = (const float*)d_in[0];
    const float* q_in = (const float*)d_in[1];
    const float* v_in = (const float*)d_in[2];
    const float* w_q  = (const float*)d_in[3];
    const float* b_q  = (const float*)d_in[4];
    const float* w_k  = (const float*)d_in[5];
    const float* b_k  = (const float*)d_in[6];
    const float* w_v  = (const float*)d_in[7];
    const float* b_v  = (const float*)d_in[8];
    const float* w_o  = (const float*)d_in[9];
    const float* b_o  = (const float*)d_in[10];
    float* out = (float*)d_out;

    float *Qp, *Kp, *Vp, *Ap;
    cudaGetSymbolAddress((void**)&Qp, g_Q);
    cudaGetSymbolAddress((void**)&Kp, g_K);
    cudaGetSymbolAddress((void**)&Vp, g_V);
    cudaGetSymbolAddress((void**)&Ap, g_A);

    const dim3 gemm_grid(32, 8);    // M/128 x N/128
    sgemm_bias<<<gemm_grid, 256>>>(q_in, w_q, b_q, Qp, 1);
    sgemm_bias<<<gemm_grid, 256>>>(k_in, w_k, b_k, Kp, 1);
    sgemm_bias<<<gemm_grid, 256>>>(v_in, w_v, b_v, Vp, 1);

    attn_fwd<<<dim3(32, 32), 256>>>();

    sgemm_bias<<<gemm_grid, 256>>>(Ap, w_o, b_o, out, 0);
}

// round 3
// speedup vs baseline: 1.7778x; 1.7778x over previous
#include <cuda_runtime.h>
#include <cuda_bf16.h>
#include <cstdint>

#define Bn 2
#define Sn 2048
#define Dn 1024
#define Hn 16
#define DKn 64

// Scratch: projected Q/K/V in [B,H,S,DK] layout, attention output in [B,S,D]
__device__ float g_Q[(size_t)Bn * Hn * Sn * DKn];
__device__ float g_K[(size_t)Bn * Hn * Sn * DKn];
__device__ float g_V[(size_t)Bn * Hn * Sn * DKn];
__device__ float g_A[(size_t)Bn * Sn * Dn];

// ---------------------------------------------------------------------------
// Helpers
// ---------------------------------------------------------------------------
__device__ __forceinline__ uint32_t smem_u32(const void* p) {
    uint32_t a;
    asm("{ .reg .u64 t; cvta.to.shared.u64 t, %1; cvt.u32.u64 %0, t; }"
        : "=r"(a) : "l"(p));
    return a;
}

__device__ __forceinline__ void ldsm_x4(uint32_t (&r)[4], uint32_t addr) {
    asm volatile("ldmatrix.sync.aligned.m8n8.x4.shared.b16 {%0,%1,%2,%3}, [%4];"
        : "=r"(r[0]), "=r"(r[1]), "=r"(r[2]), "=r"(r[3]) : "r"(addr));
}

__device__ __forceinline__ void mma16816(float (&d)[4], const uint32_t (&a)[4],
                                         uint32_t b0, uint32_t b1) {
    asm volatile(
        "mma.sync.aligned.m16n8k16.row.col.f32.bf16.bf16.f32 "
        "{%0,%1,%2,%3}, {%4,%5,%6,%7}, {%8,%9}, {%0,%1,%2,%3};"
        : "+f"(d[0]), "+f"(d[1]), "+f"(d[2]), "+f"(d[3])
        : "r"(a[0]), "r"(a[1]), "r"(a[2]), "r"(a[3]), "r"(b0), "r"(b1));
}

// Split one float4 into hi/lo bf16x2 pairs
__device__ __forceinline__ void split4(float4 v, uint2& hi, uint2& lo) {
    __nv_bfloat16 h0 = __float2bfloat16_rn(v.x);
    __nv_bfloat16 h1 = __float2bfloat16_rn(v.y);
    __nv_bfloat16 h2 = __float2bfloat16_rn(v.z);
    __nv_bfloat16 h3 = __float2bfloat16_rn(v.w);
    __nv_bfloat16 l0 = __float2bfloat16_rn(v.x - __bfloat162float(h0));
    __nv_bfloat16 l1 = __float2bfloat16_rn(v.y - __bfloat162float(h1));
    __nv_bfloat16 l2 = __float2bfloat16_rn(v.z - __bfloat162float(h2));
    __nv_bfloat16 l3 = __float2bfloat16_rn(v.w - __bfloat162float(h3));
    hi.x = ((uint32_t)__bfloat16_as_ushort(h1) << 16) | __bfloat16_as_ushort(h0);
    hi.y = ((uint32_t)__bfloat16_as_ushort(h3) << 16) | __bfloat16_as_ushort(h2);
    lo.x = ((uint32_t)__bfloat16_as_ushort(l1) << 16) | __bfloat16_as_ushort(l0);
    lo.y = ((uint32_t)__bfloat16_as_ushort(l3) << 16) | __bfloat16_as_ushort(l2);
}

// ---------------------------------------------------------------------------
// HMMA GEMM with bias + 3-term bf16 split (fp32-class precision)
// Y[m,n] = sum_k X[m,k]*W[n,k] + bias[n].  M=4096, N=K=1024.
// Tile 128x128, BK=32, 256 threads, 8 warps in 4(M) x 2(N), warp tile 32x64.
// Smem: padded bf16 [128][40] per matrix (hi/lo for A and B), double-buffered.
// ---------------------------------------------------------------------------
#define LDA_S   80                       // bytes per smem row (40 bf16)
#define MAT_SZ  (128 * LDA_S)            // 10240 B
#define STG_SZ  (4 * MAT_SZ)             // Ah, Al, Bh, Bl
#define GEMM_SMEM (2 * STG_SZ)           // 81920 B

__global__ __launch_bounds__(256, 1) void gemm_tc(
    const float* __restrict__ X,
    const float* __restrict__ W,
    const float* __restrict__ bias,
    float* __restrict__ Y,
    int permute)
{
    extern __shared__ char sm[];
    const uint32_t sb = smem_u32(sm);
    const int tid  = threadIdx.x;
    const int lane = tid & 31;
    const int wid  = tid >> 5;
    const int wm   = wid >> 1;           // 0..3 (M)
    const int wn   = wid & 1;            // 0..1 (N)

    const int m0 = blockIdx.x * 128;
    const int n0 = blockIdx.y * 128;
    const float* Ag = X + (size_t)m0 * Dn;
    const float* Bg = W + (size_t)n0 * Dn;

    // Per-thread global load indices: 4 float4 each for A and B
    const int rowA[4] = { (tid + 0) >> 3, (tid + 256) >> 3,
                          (tid + 512) >> 3, (tid + 768) >> 3 };
    const int c4 = (tid & 7) * 4;        // float col within 32-wide slab

    // ldmatrix base offsets (within a stage) for this warp
    // A: row = wm*32 + mf*16 + lane%16 ; byte = ks*32 + (lane/16)*16
    const uint32_t a_row = wm * 32 + (lane & 15);
    const uint32_t a_byt = (lane >> 4) * 16;
    // B: row = wn*64 + nq*16 + (lane&7) + ((lane>>4)<<3) ; byte = ks*32 + ((lane>>3)&1)*16
    const uint32_t b_row = wn * 64 + (lane & 7) + ((lane >> 4) << 3);
    const uint32_t b_byt = ((lane >> 3) & 1) * 16;

    float acc[2][8][4];
#pragma unroll
    for (int i = 0; i < 2; i++)
#pragma unroll
        for (int j = 0; j < 8; j++)
#pragma unroll
            for (int k = 0; k < 4; k++) acc[i][j][k] = 0.f;

    float4 ra[4], rb[4];
    // Prologue: load slab 0
#pragma unroll
    for (int i = 0; i < 4; i++) {
        ra[i] = *(const float4*)(Ag + (size_t)rowA[i] * Dn + c4);
        rb[i] = *(const float4*)(Bg + (size_t)rowA[i] * Dn + c4);
    }
    {
        char* st = sm;
#pragma unroll
        for (int i = 0; i < 4; i++) {
            uint2 hi, lo;
            const uint32_t off = rowA[i] * LDA_S + (tid & 7) * 8;
            split4(ra[i], hi, lo);
            *(uint2*)(st + off) = hi;
            *(uint2*)(st + MAT_SZ + off) = lo;
            split4(rb[i], hi, lo);
            *(uint2*)(st + 2 * MAT_SZ + off) = hi;
            *(uint2*)(st + 3 * MAT_SZ + off) = lo;
        }
    }
    __syncthreads();

#pragma unroll 1
    for (int s = 0; s < 32; s++) {
        // Issue next slab's global loads early (hidden behind mma)
        if (s + 1 < 32) {
            const int k0 = (s + 1) * 32 + c4;
#pragma unroll
            for (int i = 0; i < 4; i++) {
                ra[i] = *(const float4*)(Ag + (size_t)rowA[i] * Dn + k0);
                rb[i] = *(const float4*)(Bg + (size_t)rowA[i] * Dn + k0);
            }
        }

        // Compute on current buffer
        const uint32_t stg = sb + (s & 1) * STG_SZ;
#pragma unroll
        for (int ks = 0; ks < 2; ks++) {
            uint32_t ah[2][4], al[2][4], bh[4][4], bl[4][4];
#pragma unroll
            for (int mf = 0; mf < 2; mf++) {
                const uint32_t ao = stg + (a_row + mf * 16) * LDA_S + ks * 32 + a_byt;
                ldsm_x4(ah[mf], ao);
                ldsm_x4(al[mf], ao + MAT_SZ);
            }
#pragma unroll
            for (int nq = 0; nq < 4; nq++) {
                const uint32_t bo = stg + 2 * MAT_SZ +
                                    (b_row + nq * 16) * LDA_S + ks * 32 + b_byt;
                ldsm_x4(bh[nq], bo);
                ldsm_x4(bl[nq], bo + MAT_SZ);
            }
#pragma unroll
            for (int mf = 0; mf < 2; mf++)
#pragma unroll
                for (int nq = 0; nq < 4; nq++) {
                    mma16816(acc[mf][nq * 2 + 0], ah[mf], bh[nq][0], bh[nq][1]);
                    mma16816(acc[mf][nq * 2 + 1], ah[mf], bh[nq][2], bh[nq][3]);
                    mma16816(acc[mf][nq * 2 + 0], ah[mf], bl[nq][0], bl[nq][1]);
                    mma16816(acc[mf][nq * 2 + 1], ah[mf], bl[nq][2], bl[nq][3]);
                    mma16816(acc[mf][nq * 2 + 0], al[mf], bh[nq][0], bh[nq][1]);
                    mma16816(acc[mf][nq * 2 + 1], al[mf], bh[nq][2], bh[nq][3]);
                }
        }

        // Convert+store next slab into the other buffer
        if (s + 1 < 32) {
            char* st = sm + ((s + 1) & 1) * STG_SZ;
#pragma unroll
            for (int i = 0; i < 4; i++) {
                uint2 hi, lo;
                const uint32_t off = rowA[i] * LDA_S + (tid & 7) * 8;
                split4(ra[i], hi, lo);
                *(uint2*)(st + off) = hi;
                *(uint2*)(st + MAT_SZ + off) = lo;
                split4(rb[i], hi, lo);
                *(uint2*)(st + 2 * MAT_SZ + off) = hi;
                *(uint2*)(st + 3 * MAT_SZ + off) = lo;
            }
        }
        __syncthreads();
    }

    // Epilogue: bias add + store (optionally permuted to [B,H,S,DK])
#pragma unroll
    for (int mf = 0; mf < 2; mf++) {
        const int mr = m0 + wm * 32 + mf * 16 + (lane >> 2);
#pragma unroll
        for (int nf = 0; nf < 8; nf++) {
            const int c0 = n0 + wn * 64 + nf * 8 + (lane & 3) * 2;
            const float b0 = bias[c0], b1 = bias[c0 + 1];
#pragma unroll
            for (int rr = 0; rr < 2; rr++) {
                const int m = mr + rr * 8;
                const float v0 = acc[mf][nf][rr * 2 + 0] + b0;
                const float v1 = acc[mf][nf][rr * 2 + 1] + b1;
                if (permute) {
                    const int b = m >> 11, srow = m & (Sn - 1);
                    const int h = c0 >> 6, dk = c0 & 63;
                    float* dst = Y + (((size_t)(b * Hn + h)) * Sn + srow) * DKn + dk;
                    dst[0] = v0; dst[1] = v1;
                } else {
                    float* dst = Y + (size_t)m * Dn + c0;
                    dst[0] = v0; dst[1] = v1;
                }
            }
        }
    }
}

// ---------------------------------------------------------------------------
// Causal flash attention (round-1 version, known good: 641 us)
// ---------------------------------------------------------------------------
__global__ __launch_bounds__(256) void attn_fwd()
{
    __shared__ float Qs[64][64];
    __shared__ float KP[64][64];
    __shared__ float Vs[64][64];

    const int qt  = blockIdx.x;
    const int bh  = blockIdx.y;
    const int tid = threadIdx.x;
    const int tx  = tid & 15;
    const int ty  = tid >> 4;

    const float* Qg = g_Q + (size_t)bh * Sn * DKn;
    const float* Kg = g_K + (size_t)bh * Sn * DKn;
    const float* Vg = g_V + (size_t)bh * Sn * DKn;
    const int q0 = qt * 64;

    {
        const int row = tid & 63, quad = tid >> 6;
        const float* src = Qg + (size_t)(q0 + row) * DKn + quad * 16;
#pragma unroll
        for (int w = 0; w < 4; w++) {
            float4 v = *(const float4*)(src + w * 4);
            const int k = quad * 16 + w * 4;
            Qs[k + 0][row] = v.x; Qs[k + 1][row] = v.y;
            Qs[k + 2][row] = v.z; Qs[k + 3][row] = v.w;
        }
    }

    float m[4], l[4], o[4][4];
#pragma unroll
    for (int i = 0; i < 4; i++) {
        m[i] = -1e30f; l[i] = 0.f;
#pragma unroll
        for (int j = 0; j < 4; j++) o[i][j] = 0.f;
    }
    __syncthreads();

    for (int kt = 0; kt <= qt; kt++) {
        const int k0 = kt * 64;
        {
            const int row = tid & 63, quad = tid >> 6;
            const float* src = Kg + (size_t)(k0 + row) * DKn + quad * 16;
#pragma unroll
            for (int w = 0; w < 4; w++) {
                float4 v = *(const float4*)(src + w * 4);
                const int k = quad * 16 + w * 4;
                KP[k + 0][row] = v.x; KP[k + 1][row] = v.y;
                KP[k + 2][row] = v.z; KP[k + 3][row] = v.w;
            }
#pragma unroll
            for (int w = 0; w < 4; w++) {
                const int off = w * 1024 + tid * 4;
                const int r = off >> 6, cc = off & 63;
                *(float4*)&Vs[r][cc] =
                    *(const float4*)(Vg + (size_t)(k0 + r) * DKn + cc);
            }
        }
        __syncthreads();

        float s[4][4];
#pragma unroll
        for (int i = 0; i < 4; i++)
#pragma unroll
            for (int j = 0; j < 4; j++) s[i][j] = 0.f;

#pragma unroll
        for (int kk = 0; kk < 64; kk++) {
            float4 a = *(const float4*)&Qs[kk][ty * 4];
            float4 b = *(const float4*)&KP[kk][tx * 4];
            float av[4] = {a.x, a.y, a.z, a.w};
            float bv[4] = {b.x, b.y, b.z, b.w};
#pragma unroll
            for (int i = 0; i < 4; i++)
#pragma unroll
                for (int j = 0; j < 4; j++)
                    s[i][j] = fmaf(av[i], bv[j], s[i][j]);
        }

        const float scale = 0.125f;
        const bool diag = (kt == qt);
#pragma unroll
        for (int i = 0; i < 4; i++) {
            const int qrow = q0 + ty * 4 + i;
#pragma unroll
            for (int j = 0; j < 4; j++) {
                float v = s[i][j] * scale;
                if (diag && (k0 + tx * 4 + j > qrow)) v = -1e30f;
                s[i][j] = v;
            }
        }

#pragma unroll
        for (int i = 0; i < 4; i++) {
            float rmax = fmaxf(fmaxf(s[i][0], s[i][1]), fmaxf(s[i][2], s[i][3]));
#pragma unroll
            for (int off = 1; off < 16; off <<= 1)
                rmax = fmaxf(rmax, __shfl_xor_sync(0xffffffffu, rmax, off));
            const float mnew  = fmaxf(m[i], rmax);
            const float alpha = __expf(m[i] - mnew);
            float rsum = 0.f;
#pragma unroll
            for (int j = 0; j < 4; j++) {
                const float p = __expf(s[i][j] - mnew);
                s[i][j] = p;
                rsum += p;
            }
#pragma unroll
            for (int off = 1; off < 16; off <<= 1)
                rsum += __shfl_xor_sync(0xffffffffu, rsum, off);
            l[i] = l[i] * alpha + rsum;
            m[i] = mnew;
#pragma unroll
            for (int j = 0; j < 4; j++) o[i][j] *= alpha;
        }

        __syncthreads();
#pragma unroll
        for (int i = 0; i < 4; i++)
            *(float4*)&KP[ty * 4 + i][tx * 4] =
                make_float4(s[i][0], s[i][1], s[i][2], s[i][3]);
        __syncthreads();

#pragma unroll
        for (int kk = 0; kk < 64; kk++) {
            float4 bv = *(const float4*)&Vs[kk][tx * 4];
#pragma unroll
            for (int i = 0; i < 4; i++) {
                const float p = KP[ty * 4 + i][kk];
                o[i][0] = fmaf(p, bv.x, o[i][0]);
                o[i][1] = fmaf(p, bv.y, o[i][1]);
                o[i][2] = fmaf(p, bv.z, o[i][2]);
                o[i][3] = fmaf(p, bv.w, o[i][3]);
            }
        }
        __syncthreads();
    }

    const int b = bh >> 4, h = bh & 15;
#pragma unroll
    for (int i = 0; i < 4; i++) {
        const float inv = 1.0f / l[i];
        const int srow = q0 + ty * 4 + i;
        float4 v = make_float4(o[i][0] * inv, o[i][1] * inv,
                               o[i][2] * inv, o[i][3] * inv);
        *(float4*)&g_A[((size_t)(b * Sn + srow)) * Dn + h * DKn + tx * 4] = v;
    }
}

// ---------------------------------------------------------------------------
extern "C" void kernel_launch(void* const* d_in, const int* in_sizes, int n_in,
                              void* d_out, int out_size)
{
    const float* k_in = (const float*)d_in[0];
    const float* q_in = (const float*)d_in[1];
    const float* v_in = (const float*)d_in[2];
    const float* w_q  = (const float*)d_in[3];
    const float* b_q  = (const float*)d_in[4];
    const float* w_k  = (const float*)d_in[5];
    const float* b_k  = (const float*)d_in[6];
    const float* w_v  = (const float*)d_in[7];
    const float* b_v  = (const float*)d_in[8];
    const float* w_o  = (const float*)d_in[9];
    const float* b_o  = (const float*)d_in[10];
    float* out = (float*)d_out;

    float *Qp, *Kp, *Vp, *Ap;
    cudaGetSymbolAddress((void**)&Qp, g_Q);
    cudaGetSymbolAddress((void**)&Kp, g_K);
    cudaGetSymbolAddress((void**)&Vp, g_V);
    cudaGetSymbolAddress((void**)&Ap, g_A);

    cudaFuncSetAttribute(gemm_tc, cudaFuncAttributeMaxDynamicSharedMemorySize,
                         GEMM_SMEM);

    const dim3 gg(32, 8);
    gemm_tc<<<gg, 256, GEMM_SMEM>>>(q_in, w_q, b_q, Qp, 1);
    gemm_tc<<<gg, 256, GEMM_SMEM>>>(k_in, w_k, b_k, Kp, 1);
    gemm_tc<<<gg, 256, GEMM_SMEM>>>(v_in, w_v, b_v, Vp, 1);

    attn_fwd<<<dim3(32, 32), 256>>>();

    gemm_tc<<<gg, 256, GEMM_SMEM>>>(Ap, w_o, b_o, out, 0);
}

// round 4
// speedup vs baseline: 1.8119x; 1.0192x over previous
#include <cuda_runtime.h>
#include <cuda_bf16.h>
#include <cstdint>

#define Bn 2
#define Sn 2048
#define Dn 1024
#define Hn 16
#define DKn 64

// Scratch: projected Q/K/V in [B,H,S,DK] layout, attention output in [B,S,D]
__device__ float g_Q[(size_t)Bn * Hn * Sn * DKn];
__device__ float g_K[(size_t)Bn * Hn * Sn * DKn];
__device__ float g_V[(size_t)Bn * Hn * Sn * DKn];
__device__ float g_A[(size_t)Bn * Sn * Dn];

// ---------------------------------------------------------------------------
// Helpers
// ---------------------------------------------------------------------------
__device__ __forceinline__ uint32_t smem_u32(const void* p) {
    uint32_t a;
    asm("{ .reg .u64 t; cvta.to.shared.u64 t, %1; cvt.u32.u64 %0, t; }"
        : "=r"(a) : "l"(p));
    return a;
}

__device__ __forceinline__ void ldsm_x4(uint32_t (&r)[4], uint32_t addr) {
    asm volatile("ldmatrix.sync.aligned.m8n8.x4.shared.b16 {%0,%1,%2,%3}, [%4];"
        : "=r"(r[0]), "=r"(r[1]), "=r"(r[2]), "=r"(r[3]) : "r"(addr));
}

__device__ __forceinline__ void mma16816(float (&d)[4], const uint32_t (&a)[4],
                                         uint32_t b0, uint32_t b1) {
    asm volatile(
        "mma.sync.aligned.m16n8k16.row.col.f32.bf16.bf16.f32 "
        "{%0,%1,%2,%3}, {%4,%5,%6,%7}, {%8,%9}, {%0,%1,%2,%3};"
        : "+f"(d[0]), "+f"(d[1]), "+f"(d[2]), "+f"(d[3])
        : "r"(a[0]), "r"(a[1]), "r"(a[2]), "r"(a[3]), "r"(b0), "r"(b1));
}

// Split one float4 into hi/lo bf16x2 pairs
__device__ __forceinline__ void split4(float4 v, uint2& hi, uint2& lo) {
    __nv_bfloat16 h0 = __float2bfloat16_rn(v.x);
    __nv_bfloat16 h1 = __float2bfloat16_rn(v.y);
    __nv_bfloat16 h2 = __float2bfloat16_rn(v.z);
    __nv_bfloat16 h3 = __float2bfloat16_rn(v.w);
    __nv_bfloat16 l0 = __float2bfloat16_rn(v.x - __bfloat162float(h0));
    __nv_bfloat16 l1 = __float2bfloat16_rn(v.y - __bfloat162float(h1));
    __nv_bfloat16 l2 = __float2bfloat16_rn(v.z - __bfloat162float(h2));
    __nv_bfloat16 l3 = __float2bfloat16_rn(v.w - __bfloat162float(h3));
    hi.x = ((uint32_t)__bfloat16_as_ushort(h1) << 16) | __bfloat16_as_ushort(h0);
    hi.y = ((uint32_t)__bfloat16_as_ushort(h3) << 16) | __bfloat16_as_ushort(h2);
    lo.x = ((uint32_t)__bfloat16_as_ushort(l1) << 16) | __bfloat16_as_ushort(l0);
    lo.y = ((uint32_t)__bfloat16_as_ushort(l3) << 16) | __bfloat16_as_ushort(l2);
}

// ---------------------------------------------------------------------------
// HMMA GEMM with bias + 3-term bf16 split (fp32-class precision)
// Y[m,n] = sum_k X[m,k]*W[n,k] + bias[n].  M=4096, N=K=1024.
// Tile 128x128, BK=32, 256 threads, 8 warps in 4(M) x 2(N), warp tile 32x64.
// Smem: padded bf16 [128][40] per matrix (hi/lo for A and B), double-buffered.
// ---------------------------------------------------------------------------
#define LDA_S   80                       // bytes per smem row (40 bf16)
#define MAT_SZ  (128 * LDA_S)            // 10240 B
#define STG_SZ  (4 * MAT_SZ)             // Ah, Al, Bh, Bl
#define GEMM_SMEM (2 * STG_SZ)           // 81920 B

__global__ __launch_bounds__(256, 1) void gemm_tc(
    const float* __restrict__ X,
    const float* __restrict__ W,
    const float* __restrict__ bias,
    float* __restrict__ Y,
    int permute)
{
    extern __shared__ char sm[];
    const uint32_t sb = smem_u32(sm);
    const int tid  = threadIdx.x;
    const int lane = tid & 31;
    const int wid  = tid >> 5;
    const int wm   = wid >> 1;           // 0..3 (M)
    const int wn   = wid & 1;            // 0..1 (N)

    const int m0 = blockIdx.x * 128;
    const int n0 = blockIdx.y * 128;
    const float* Ag = X + (size_t)m0 * Dn;
    const float* Bg = W + (size_t)n0 * Dn;

    // Per-thread global load indices: 4 float4 each for A and B
    const int rowA[4] = { (tid + 0) >> 3, (tid + 256) >> 3,
                          (tid + 512) >> 3, (tid + 768) >> 3 };
    const int c4 = (tid & 7) * 4;        // float col within 32-wide slab

    // ldmatrix base offsets (within a stage) for this warp
    // A: row = wm*32 + mf*16 + lane%16 ; byte = ks*32 + (lane/16)*16
    const uint32_t a_row = wm * 32 + (lane & 15);
    const uint32_t a_byt = (lane >> 4) * 16;
    // B: row = wn*64 + nq*16 + (lane&7) + ((lane>>4)<<3) ; byte = ks*32 + ((lane>>3)&1)*16
    const uint32_t b_row = wn * 64 + (lane & 7) + ((lane >> 4) << 3);
    const uint32_t b_byt = ((lane >> 3) & 1) * 16;

    float acc[2][8][4];
#pragma unroll
    for (int i = 0; i < 2; i++)
#pragma unroll
        for (int j = 0; j < 8; j++)
#pragma unroll
            for (int k = 0; k < 4; k++) acc[i][j][k] = 0.f;

    float4 ra[4], rb[4];
    // Prologue: load slab 0
#pragma unroll
    for (int i = 0; i < 4; i++) {
        ra[i] = *(const float4*)(Ag + (size_t)rowA[i] * Dn + c4);
        rb[i] = *(const float4*)(Bg + (size_t)rowA[i] * Dn + c4);
    }
    {
        char* st = sm;
#pragma unroll
        for (int i = 0; i < 4; i++) {
            uint2 hi, lo;
            const uint32_t off = rowA[i] * LDA_S + (tid & 7) * 8;
            split4(ra[i], hi, lo);
            *(uint2*)(st + off) = hi;
            *(uint2*)(st + MAT_SZ + off) = lo;
            split4(rb[i], hi, lo);
            *(uint2*)(st + 2 * MAT_SZ + off) = hi;
            *(uint2*)(st + 3 * MAT_SZ + off) = lo;
        }
    }
    __syncthreads();

#pragma unroll 1
    for (int s = 0; s < 32; s++) {
        // Issue next slab's global loads early (hidden behind mma)
        if (s + 1 < 32) {
            const int k0 = (s + 1) * 32 + c4;
#pragma unroll
            for (int i = 0; i < 4; i++) {
                ra[i] = *(const float4*)(Ag + (size_t)rowA[i] * Dn + k0);
                rb[i] = *(const float4*)(Bg + (size_t)rowA[i] * Dn + k0);
            }
        }

        // Compute on current buffer
        const uint32_t stg = sb + (s & 1) * STG_SZ;
#pragma unroll
        for (int ks = 0; ks < 2; ks++) {
            uint32_t ah[2][4], al[2][4], bh[4][4], bl[4][4];
#pragma unroll
            for (int mf = 0; mf < 2; mf++) {
                const uint32_t ao = stg + (a_row + mf * 16) * LDA_S + ks * 32 + a_byt;
                ldsm_x4(ah[mf], ao);
                ldsm_x4(al[mf], ao + MAT_SZ);
            }
#pragma unroll
            for (int nq = 0; nq < 4; nq++) {
                const uint32_t bo = stg + 2 * MAT_SZ +
                                    (b_row + nq * 16) * LDA_S + ks * 32 + b_byt;
                ldsm_x4(bh[nq], bo);
                ldsm_x4(bl[nq], bo + MAT_SZ);
            }
#pragma unroll
            for (int mf = 0; mf < 2; mf++)
#pragma unroll
                for (int nq = 0; nq < 4; nq++) {
                    mma16816(acc[mf][nq * 2 + 0], ah[mf], bh[nq][0], bh[nq][1]);
                    mma16816(acc[mf][nq * 2 + 1], ah[mf], bh[nq][2], bh[nq][3]);
                    mma16816(acc[mf][nq * 2 + 0], ah[mf], bl[nq][0], bl[nq][1]);
                    mma16816(acc[mf][nq * 2 + 1], ah[mf], bl[nq][2], bl[nq][3]);
                    mma16816(acc[mf][nq * 2 + 0], al[mf], bh[nq][0], bh[nq][1]);
                    mma16816(acc[mf][nq * 2 + 1], al[mf], bh[nq][2], bh[nq][3]);
                }
        }

        // Convert+store next slab into the other buffer
        if (s + 1 < 32) {
            char* st = sm + ((s + 1) & 1) * STG_SZ;
#pragma unroll
            for (int i = 0; i < 4; i++) {
                uint2 hi, lo;
                const uint32_t off = rowA[i] * LDA_S + (tid & 7) * 8;
                split4(ra[i], hi, lo);
                *(uint2*)(st + off) = hi;
                *(uint2*)(st + MAT_SZ + off) = lo;
                split4(rb[i], hi, lo);
                *(uint2*)(st + 2 * MAT_SZ + off) = hi;
                *(uint2*)(st + 3 * MAT_SZ + off) = lo;
            }
        }
        __syncthreads();
    }

    // Epilogue: bias add + store (optionally permuted to [B,H,S,DK])
#pragma unroll
    for (int mf = 0; mf < 2; mf++) {
        const int mr = m0 + wm * 32 + mf * 16 + (lane >> 2);
#pragma unroll
        for (int nf = 0; nf < 8; nf++) {
            const int c0 = n0 + wn * 64 + nf * 8 + (lane & 3) * 2;
            const float b0 = bias[c0], b1 = bias[c0 + 1];
#pragma unroll
            for (int rr = 0; rr < 2; rr++) {
                const int m = mr + rr * 8;
                const float v0 = acc[mf][nf][rr * 2 + 0] + b0;
                const float v1 = acc[mf][nf][rr * 2 + 1] + b1;
                if (permute) {
                    const int b = m >> 11, srow = m & (Sn - 1);
                    const int h = c0 >> 6, dk = c0 & 63;
                    float* dst = Y + (((size_t)(b * Hn + h)) * Sn + srow) * DKn + dk;
                    dst[0] = v0; dst[1] = v1;
                } else {
                    float* dst = Y + (size_t)m * Dn + c0;
                    dst[0] = v0; dst[1] = v1;
                }
            }
        }
    }
}

// ---------------------------------------------------------------------------
// Causal flash attention (round-1 version, known good: 641 us)
// ---------------------------------------------------------------------------
__global__ __launch_bounds__(256) void attn_fwd()
{
    __shared__ float Qs[64][64];
    __shared__ float KP[64][64];
    __shared__ float Vs[64][64];

    const int qt  = blockIdx.x;
    const int bh  = blockIdx.y;
    const int tid = threadIdx.x;
    const int tx  = tid & 15;
    const int ty  = tid >> 4;

    const float* Qg = g_Q + (size_t)bh * Sn * DKn;
    const float* Kg = g_K + (size_t)bh * Sn * DKn;
    const float* Vg = g_V + (size_t)bh * Sn * DKn;
    const int q0 = qt * 64;

    {
        const int row = tid & 63, quad = tid >> 6;
        const float* src = Qg + (size_t)(q0 + row) * DKn + quad * 16;
#pragma unroll
        for (int w = 0; w < 4; w++) {
            float4 v = *(const float4*)(src + w * 4);
            const int k = quad * 16 + w * 4;
            Qs[k + 0][row] = v.x; Qs[k + 1][row] = v.y;
            Qs[k + 2][row] = v.z; Qs[k + 3][row] = v.w;
        }
    }

    float m[4], l[4], o[4][4];
#pragma unroll
    for (int i = 0; i < 4; i++) {
        m[i] = -1e30f; l[i] = 0.f;
#pragma unroll
        for (int j = 0; j < 4; j++) o[i][j] = 0.f;
    }
    __syncthreads();

    for (int kt = 0; kt <= qt; kt++) {
        const int k0 = kt * 64;
        {
            const int row = tid & 63, quad = tid >> 6;
            const float* src = Kg + (size_t)(k0 + row) * DKn + quad * 16;
#pragma unroll
            for (int w = 0; w < 4; w++) {
                float4 v = *(const float4*)(src + w * 4);
                const int k = quad * 16 + w * 4;
                KP[k + 0][row] = v.x; KP[k + 1][row] = v.y;
                KP[k + 2][row] = v.z; KP[k + 3][row] = v.w;
            }
#pragma unroll
            for (int w = 0; w < 4; w++) {
                const int off = w * 1024 + tid * 4;
                const int r = off >> 6, cc = off & 63;
                *(float4*)&Vs[r][cc] =
                    *(const float4*)(Vg + (size_t)(k0 + r) * DKn + cc);
            }
        }
        __syncthreads();

        float s[4][4];
#pragma unroll
        for (int i = 0; i < 4; i++)
#pragma unroll
            for (int j = 0; j < 4; j++) s[i][j] = 0.f;

#pragma unroll
        for (int kk = 0; kk < 64; kk++) {
            float4 a = *(const float4*)&Qs[kk][ty * 4];
            float4 b = *(const float4*)&KP[kk][tx * 4];
            float av[4] = {a.x, a.y, a.z, a.w};
            float bv[4] = {b.x, b.y, b.z, b.w};
#pragma unroll
            for (int i = 0; i < 4; i++)
#pragma unroll
                for (int j = 0; j < 4; j++)
                    s[i][j] = fmaf(av[i], bv[j], s[i][j]);
        }

        const float scale = 0.125f;
        const bool diag = (kt == qt);
#pragma unroll
        for (int i = 0; i < 4; i++) {
            const int qrow = q0 + ty * 4 + i;
#pragma unroll
            for (int j = 0; j < 4; j++) {
                float v = s[i][j] * scale;
                if (diag && (k0 + tx * 4 + j > qrow)) v = -1e30f;
                s[i][j] = v;
            }
        }

#pragma unroll
        for (int i = 0; i < 4; i++) {
            float rmax = fmaxf(fmaxf(s[i][0], s[i][1]), fmaxf(s[i][2], s[i][3]));
#pragma unroll
            for (int off = 1; off < 16; off <<= 1)
                rmax = fmaxf(rmax, __shfl_xor_sync(0xffffffffu, rmax, off));
            const float mnew  = fmaxf(m[i], rmax);
            const float alpha = __expf(m[i] - mnew);
            float rsum = 0.f;
#pragma unroll
            for (int j = 0; j < 4; j++) {
                const float p = __expf(s[i][j] - mnew);
                s[i][j] = p;
                rsum += p;
            }
#pragma unroll
            for (int off = 1; off < 16; off <<= 1)
                rsum += __shfl_xor_sync(0xffffffffu, rsum, off);
            l[i] = l[i] * alpha + rsum;
            m[i] = mnew;
#pragma unroll
            for (int j = 0; j < 4; j++) o[i][j] *= alpha;
        }

        __syncthreads();
#pragma unroll
        for (int i = 0; i < 4; i++)
            *(float4*)&KP[ty * 4 + i][tx * 4] =
                make_float4(s[i][0], s[i][1], s[i][2], s[i][3]);
        __syncthreads();

#pragma unroll
        for (int kk = 0; kk < 64; kk++) {
            float4 bv = *(const float4*)&Vs[kk][tx * 4];
#pragma unroll
            for (int i = 0; i < 4; i++) {
                const float p = KP[ty * 4 + i][kk];
                o[i][0] = fmaf(p, bv.x, o[i][0]);
                o[i][1] = fmaf(p, bv.y, o[i][1]);
                o[i][2] = fmaf(p, bv.z, o[i][2]);
                o[i][3] = fmaf(p, bv.w, o[i][3]);
            }
        }
        __syncthreads();
    }

    const int b = bh >> 4, h = bh & 15;
#pragma unroll
    for (int i = 0; i < 4; i++) {
        const float inv = 1.0f / l[i];
        const int srow = q0 + ty * 4 + i;
        float4 v = make_float4(o[i][0] * inv, o[i][1] * inv,
                               o[i][2] * inv, o[i][3] * inv);
        *(float4*)&g_A[((size_t)(b * Sn + srow)) * Dn + h * DKn + tx * 4] = v;
    }
}

// ---------------------------------------------------------------------------
extern "C" void kernel_launch(void* const* d_in, const int* in_sizes, int n_in,
                              void* d_out, int out_size)
{
    const float* k_in = (const float*)d_in[0];
    const float* q_in = (const float*)d_in[1];
    const float* v_in = (const float*)d_in[2];
    const float* w_q  = (const float*)d_in[3];
    const float* b_q  = (const float*)d_in[4];
    const float* w_k  = (const float*)d_in[5];
    const float* b_k  = (const float*)d_in[6];
    const float* w_v  = (const float*)d_in[7];
    const float* b_v  = (const float*)d_in[8];
    const float* w_o  = (const float*)d_in[9];
    const float* b_o  = (const float*)d_in[10];
    float* out = (float*)d_out;

    float *Qp, *Kp, *Vp, *Ap;
    cudaGetSymbolAddress((void**)&Qp, g_Q);
    cudaGetSymbolAddress((void**)&Kp, g_K);
    cudaGetSymbolAddress((void**)&Vp, g_V);
    cudaGetSymbolAddress((void**)&Ap, g_A);

    cudaFuncSetAttribute(gemm_tc, cudaFuncAttributeMaxDynamicSharedMemorySize,
                         GEMM_SMEM);

    const dim3 gg(32, 8);
    gemm_tc<<<gg, 256, GEMM_SMEM>>>(q_in, w_q, b_q, Qp, 1);
    gemm_tc<<<gg, 256, GEMM_SMEM>>>(k_in, w_k, b_k, Kp, 1);
    gemm_tc<<<gg, 256, GEMM_SMEM>>>(v_in, w_v, b_v, Vp, 1);

    attn_fwd<<<dim3(32, 32), 256>>>();

    gemm_tc<<<gg, 256, GEMM_SMEM>>>(Ap, w_o, b_o, out, 0);
}

// round 5
// speedup vs baseline: 2.4812x; 1.3694x over previous
#include <cuda_runtime.h>
#include <cuda_bf16.h>
#include <cstdint>

#define Bn 2
#define Sn 2048
#define Dn 1024
#define Hn 16
#define DKn 64

// Scratch: projected Q/K/V in [B,H,S,DK] layout, attention output in [B,S,D]
__device__ float g_Q[(size_t)Bn * Hn * Sn * DKn];
__device__ float g_K[(size_t)Bn * Hn * Sn * DKn];
__device__ float g_V[(size_t)Bn * Hn * Sn * DKn];
__device__ float g_A[(size_t)Bn * Sn * Dn];

// ---------------------------------------------------------------------------
// Helpers
// ---------------------------------------------------------------------------
__device__ __forceinline__ uint32_t smem_u32(const void* p) {
    uint32_t a;
    asm("{ .reg .u64 t; cvta.to.shared.u64 t, %1; cvt.u32.u64 %0, t; }"
        : "=r"(a) : "l"(p));
    return a;
}

__device__ __forceinline__ void ldsm_x4(uint32_t (&r)[4], uint32_t addr) {
    asm volatile("ldmatrix.sync.aligned.m8n8.x4.shared.b16 {%0,%1,%2,%3}, [%4];"
        : "=r"(r[0]), "=r"(r[1]), "=r"(r[2]), "=r"(r[3]) : "r"(addr));
}

__device__ __forceinline__ void ldsm_x4_t(uint32_t (&r)[4], uint32_t addr) {
    asm volatile("ldmatrix.sync.aligned.m8n8.x4.trans.shared.b16 {%0,%1,%2,%3}, [%4];"
        : "=r"(r[0]), "=r"(r[1]), "=r"(r[2]), "=r"(r[3]) : "r"(addr));
}

__device__ __forceinline__ void mma16816(float (&d)[4], const uint32_t (&a)[4],
                                         uint32_t b0, uint32_t b1) {
    asm volatile(
        "mma.sync.aligned.m16n8k16.row.col.f32.bf16.bf16.f32 "
        "{%0,%1,%2,%3}, {%4,%5,%6,%7}, {%8,%9}, {%0,%1,%2,%3};"
        : "+f"(d[0]), "+f"(d[1]), "+f"(d[2]), "+f"(d[3])
        : "r"(a[0]), "r"(a[1]), "r"(a[2]), "r"(a[3]), "r"(b0), "r"(b1));
}

// Split one float4 into hi/lo bf16x2 pairs
__device__ __forceinline__ void split4(float4 v, uint2& hi, uint2& lo) {
    __nv_bfloat16 h0 = __float2bfloat16_rn(v.x);
    __nv_bfloat16 h1 = __float2bfloat16_rn(v.y);
    __nv_bfloat16 h2 = __float2bfloat16_rn(v.z);
    __nv_bfloat16 h3 = __float2bfloat16_rn(v.w);
    __nv_bfloat16 l0 = __float2bfloat16_rn(v.x - __bfloat162float(h0));
    __nv_bfloat16 l1 = __float2bfloat16_rn(v.y - __bfloat162float(h1));
    __nv_bfloat16 l2 = __float2bfloat16_rn(v.z - __bfloat162float(h2));
    __nv_bfloat16 l3 = __float2bfloat16_rn(v.w - __bfloat162float(h3));
    hi.x = ((uint32_t)__bfloat16_as_ushort(h1) << 16) | __bfloat16_as_ushort(h0);
    hi.y = ((uint32_t)__bfloat16_as_ushort(h3) << 16) | __bfloat16_as_ushort(h2);
    lo.x = ((uint32_t)__bfloat16_as_ushort(l1) << 16) | __bfloat16_as_ushort(l0);
    lo.y = ((uint32_t)__bfloat16_as_ushort(l3) << 16) | __bfloat16_as_ushort(l2);
}

__device__ __forceinline__ uint32_t packbf(float a, float b) {
    uint32_t r = ((uint32_t)__bfloat16_as_ushort(__float2bfloat16_rn(b)) << 16) |
                 __bfloat16_as_ushort(__float2bfloat16_rn(a));
    return r;
}

// Fast exp on the FMA pipe (no MUFU). |err| ~ 2e-6 rel. Valid for x <= 0.
__device__ __forceinline__ float fexp(float x) {
    x = fmaxf(x, -80.0f);
    float n = rintf(x * 1.4426950408889634f);
    float r = fmaf(n, -0.693359375f, x);        // ln2_hi
    r = fmaf(n, 2.12194440e-4f, r);             // ln2_lo
    float p = fmaf(r, 8.3333333e-3f, 4.1666667e-2f);
    p = fmaf(r, p, 1.6666667e-1f);
    p = fmaf(r, p, 0.5f);
    p = fmaf(r, p, 1.0f);
    p = fmaf(r, p, 1.0f);
    int e = ((int)n + 127) << 23;
    return p * __int_as_float(e);
}

// ---------------------------------------------------------------------------
// HMMA GEMM with bias + 3-term bf16 split (fp32-class precision) [unchanged]
// ---------------------------------------------------------------------------
#define LDA_S   80
#define MAT_SZ  (128 * LDA_S)
#define STG_SZ  (4 * MAT_SZ)
#define GEMM_SMEM (2 * STG_SZ)

__global__ __launch_bounds__(256, 1) void gemm_tc(
    const float* __restrict__ X,
    const float* __restrict__ W,
    const float* __restrict__ bias,
    float* __restrict__ Y,
    int permute)
{
    extern __shared__ char sm[];
    const uint32_t sb = smem_u32(sm);
    const int tid  = threadIdx.x;
    const int lane = tid & 31;
    const int wid  = tid >> 5;
    const int wm   = wid >> 1;
    const int wn   = wid & 1;

    const int m0 = blockIdx.x * 128;
    const int n0 = blockIdx.y * 128;
    const float* Ag = X + (size_t)m0 * Dn;
    const float* Bg = W + (size_t)n0 * Dn;

    const int rowA[4] = { (tid + 0) >> 3, (tid + 256) >> 3,
                          (tid + 512) >> 3, (tid + 768) >> 3 };
    const int c4 = (tid & 7) * 4;

    const uint32_t a_row = wm * 32 + (lane & 15);
    const uint32_t a_byt = (lane >> 4) * 16;
    const uint32_t b_row = wn * 64 + (lane & 7) + ((lane >> 4) << 3);
    const uint32_t b_byt = ((lane >> 3) & 1) * 16;

    float acc[2][8][4];
#pragma unroll
    for (int i = 0; i < 2; i++)
#pragma unroll
        for (int j = 0; j < 8; j++)
#pragma unroll
            for (int k = 0; k < 4; k++) acc[i][j][k] = 0.f;

    float4 ra[4], rb[4];
#pragma unroll
    for (int i = 0; i < 4; i++) {
        ra[i] = *(const float4*)(Ag + (size_t)rowA[i] * Dn + c4);
        rb[i] = *(const float4*)(Bg + (size_t)rowA[i] * Dn + c4);
    }
    {
        char* st = sm;
#pragma unroll
        for (int i = 0; i < 4; i++) {
            uint2 hi, lo;
            const uint32_t off = rowA[i] * LDA_S + (tid & 7) * 8;
            split4(ra[i], hi, lo);
            *(uint2*)(st + off) = hi;
            *(uint2*)(st + MAT_SZ + off) = lo;
            split4(rb[i], hi, lo);
            *(uint2*)(st + 2 * MAT_SZ + off) = hi;
            *(uint2*)(st + 3 * MAT_SZ + off) = lo;
        }
    }
    __syncthreads();

#pragma unroll 1
    for (int s = 0; s < 32; s++) {
        if (s + 1 < 32) {
            const int k0 = (s + 1) * 32 + c4;
#pragma unroll
            for (int i = 0; i < 4; i++) {
                ra[i] = *(const float4*)(Ag + (size_t)rowA[i] * Dn + k0);
                rb[i] = *(const float4*)(Bg + (size_t)rowA[i] * Dn + k0);
            }
        }

        const uint32_t stg = sb + (s & 1) * STG_SZ;
#pragma unroll
        for (int ks = 0; ks < 2; ks++) {
            uint32_t ah[2][4], al[2][4], bh[4][4], bl[4][4];
#pragma unroll
            for (int mf = 0; mf < 2; mf++) {
                const uint32_t ao = stg + (a_row + mf * 16) * LDA_S + ks * 32 + a_byt;
                ldsm_x4(ah[mf], ao);
                ldsm_x4(al[mf], ao + MAT_SZ);
            }
#pragma unroll
            for (int nq = 0; nq < 4; nq++) {
                const uint32_t bo = stg + 2 * MAT_SZ +
                                    (b_row + nq * 16) * LDA_S + ks * 32 + b_byt;
                ldsm_x4(bh[nq], bo);
                ldsm_x4(bl[nq], bo + MAT_SZ);
            }
#pragma unroll
            for (int mf = 0; mf < 2; mf++)
#pragma unroll
                for (int nq = 0; nq < 4; nq++) {
                    mma16816(acc[mf][nq * 2 + 0], ah[mf], bh[nq][0], bh[nq][1]);
                    mma16816(acc[mf][nq * 2 + 1], ah[mf], bh[nq][2], bh[nq][3]);
                    mma16816(acc[mf][nq * 2 + 0], ah[mf], bl[nq][0], bl[nq][1]);
                    mma16816(acc[mf][nq * 2 + 1], ah[mf], bl[nq][2], bl[nq][3]);
                    mma16816(acc[mf][nq * 2 + 0], al[mf], bh[nq][0], bh[nq][1]);
                    mma16816(acc[mf][nq * 2 + 1], al[mf], bh[nq][2], bh[nq][3]);
                }
        }

        if (s + 1 < 32) {
            char* st = sm + ((s + 1) & 1) * STG_SZ;
#pragma unroll
            for (int i = 0; i < 4; i++) {
                uint2 hi, lo;
                const uint32_t off = rowA[i] * LDA_S + (tid & 7) * 8;
                split4(ra[i], hi, lo);
                *(uint2*)(st + off) = hi;
                *(uint2*)(st + MAT_SZ + off) = lo;
                split4(rb[i], hi, lo);
                *(uint2*)(st + 2 * MAT_SZ + off) = hi;
                *(uint2*)(st + 3 * MAT_SZ + off) = lo;
            }
        }
        __syncthreads();
    }

#pragma unroll
    for (int mf = 0; mf < 2; mf++) {
        const int mr = m0 + wm * 32 + mf * 16 + (lane >> 2);
#pragma unroll
        for (int nf = 0; nf < 8; nf++) {
            const int c0 = n0 + wn * 64 + nf * 8 + (lane & 3) * 2;
            const float b0 = bias[c0], b1 = bias[c0 + 1];
#pragma unroll
            for (int rr = 0; rr < 2; rr++) {
                const int m = mr + rr * 8;
                const float v0 = acc[mf][nf][rr * 2 + 0] + b0;
                const float v1 = acc[mf][nf][rr * 2 + 1] + b1;
                if (permute) {
                    const int b = m >> 11, srow = m & (Sn - 1);
                    const int h = c0 >> 6, dk = c0 & 63;
                    float* dst = Y + (((size_t)(b * Hn + h)) * Sn + srow) * DKn + dk;
                    dst[0] = v0; dst[1] = v1;
                } else {
                    float* dst = Y + (size_t)m * Dn + c0;
                    dst[0] = v0; dst[1] = v1;
                }
            }
        }
    }
}

// ---------------------------------------------------------------------------
// HMMA causal flash attention.
// 128 q-rows per CTA (8 warps x 16 rows), KV tiles of 64.
// Q kept in registers (hi/lo A-frags). K/V split bf16 hi/lo in smem.
// 3-term split on both QK^T and PV. Softmax with FMA-pipe exp.
// ---------------------------------------------------------------------------
#define LDS_B 144            // smem row stride (72 bf16)
#define Q_HI  0
#define Q_LO  18432
#define K_HI  0
#define K_LO  9216
#define V_HI  18432
#define V_LO  27648

__global__ __launch_bounds__(256) void attn_tc()
{
    __shared__ char smem[36864];
    const uint32_t sb = smem_u32(smem);
    const int tid = threadIdx.x, lane = tid & 31, wid = tid >> 5;

    const int qt = 15 - blockIdx.x;       // heavy blocks first
    const int bh = blockIdx.y;
    const int q0 = qt * 128;

    const float* Qg = g_Q + (size_t)bh * Sn * DKn;
    const float* Kg = g_K + (size_t)bh * Sn * DKn;
    const float* Vg = g_V + (size_t)bh * Sn * DKn;

    // ---- Load Q tile (128x64 fp32), split to Qh/Ql smem ----
    {
        const int row = tid >> 1;
        const int cb = (tid & 1) * 8;
        const float* src = Qg + (size_t)(q0 + row) * DKn;
#pragma unroll
        for (int i = 0; i < 8; i++) {
            float4 v = *(const float4*)(src + (cb + i) * 4);
            uint2 hi, lo;
            split4(v, hi, lo);
            const uint32_t off = row * LDS_B + (cb + i) * 8;
            *(uint2*)(smem + Q_HI + off) = hi;
            *(uint2*)(smem + Q_LO + off) = lo;
        }
    }
    __syncthreads();

    // ---- Q A-frags in registers: 4 k-chunks, hi+lo ----
    uint32_t qh[4][4], ql[4][4];
    {
        const uint32_t arow = wid * 16 + (lane & 15);
        const uint32_t abyt = (lane >> 4) * 16;
#pragma unroll
        for (int kc = 0; kc < 4; kc++) {
            const uint32_t ao = sb + arow * LDS_B + kc * 32 + abyt;
            ldsm_x4(qh[kc], ao + Q_HI);
            ldsm_x4(ql[kc], ao + Q_LO);
        }
    }

    float accO[8][4];
#pragma unroll
    for (int j = 0; j < 8; j++)
#pragma unroll
        for (int k = 0; k < 4; k++) accO[j][k] = 0.f;
    float m_lo = -1e30f, m_hi = -1e30f, l_lo = 0.f, l_hi = 0.f;

    const int r_lo = q0 + wid * 16 + (lane >> 2);
    const int r_hi = r_lo + 8;
    const uint32_t brow = (lane & 7) + ((lane >> 4) << 3);
    const uint32_t bbyt = ((lane >> 3) & 1) * 16;

    const int ntiles = 2 * qt + 2;
#pragma unroll 1
    for (int kt = 0; kt < ntiles; kt++) {
        const int k0 = kt * 64;
        __syncthreads();                 // prior tile fully consumed
        // ---- Load K,V (64x64 fp32 each), split to smem ----
        {
            const int row = tid >> 2;
            const int cb = (tid & 3) * 4;
            const float* ks = Kg + (size_t)(k0 + row) * DKn;
            const float* vs = Vg + (size_t)(k0 + row) * DKn;
#pragma unroll
            for (int i = 0; i < 4; i++) {
                float4 v = *(const float4*)(ks + (cb + i) * 4);
                uint2 hi, lo;
                split4(v, hi, lo);
                const uint32_t off = row * LDS_B + (cb + i) * 8;
                *(uint2*)(smem + K_HI + off) = hi;
                *(uint2*)(smem + K_LO + off) = lo;
                v = *(const float4*)(vs + (cb + i) * 4);
                split4(v, hi, lo);
                *(uint2*)(smem + V_HI + off) = hi;
                *(uint2*)(smem + V_LO + off) = lo;
            }
        }
        __syncthreads();

        // ---- S = Q K^T (3-term) ----
        float s[8][4];
#pragma unroll
        for (int j = 0; j < 8; j++)
#pragma unroll
            for (int k = 0; k < 4; k++) s[j][k] = 0.f;

#pragma unroll
        for (int kc = 0; kc < 4; kc++) {
#pragma unroll
            for (int nq = 0; nq < 4; nq++) {
                const uint32_t bo = sb + (brow + nq * 16) * LDS_B + kc * 32 + bbyt;
                uint32_t kh[4], kl[4];
                ldsm_x4(kh, bo + K_HI);
                ldsm_x4(kl, bo + K_LO);
                mma16816(s[nq * 2 + 0], qh[kc], kh[0], kh[1]);
                mma16816(s[nq * 2 + 1], qh[kc], kh[2], kh[3]);
                mma16816(s[nq * 2 + 0], qh[kc], kl[0], kl[1]);
                mma16816(s[nq * 2 + 1], qh[kc], kl[2], kl[3]);
                mma16816(s[nq * 2 + 0], ql[kc], kh[0], kh[1]);
                mma16816(s[nq * 2 + 1], ql[kc], kh[2], kh[3]);
            }
        }

        // ---- scale + causal mask ----
        const bool need_mask = (k0 + 63) > r_lo;
#pragma unroll
        for (int j = 0; j < 8; j++) {
            const int c = k0 + j * 8 + (lane & 3) * 2;
            s[j][0] *= 0.125f; s[j][1] *= 0.125f;
            s[j][2] *= 0.125f; s[j][3] *= 0.125f;
            if (need_mask) {
                if (c > r_lo)     s[j][0] = -1e30f;
                if (c + 1 > r_lo) s[j][1] = -1e30f;
                if (c > r_hi)     s[j][2] = -1e30f;
                if (c + 1 > r_hi) s[j][3] = -1e30f;
            }
        }

        // ---- online softmax ----
        float mx0 = -1e30f, mx1 = -1e30f;
#pragma unroll
        for (int j = 0; j < 8; j++) {
            mx0 = fmaxf(mx0, fmaxf(s[j][0], s[j][1]));
            mx1 = fmaxf(mx1, fmaxf(s[j][2], s[j][3]));
        }
        mx0 = fmaxf(mx0, __shfl_xor_sync(0xffffffffu, mx0, 1));
        mx0 = fmaxf(mx0, __shfl_xor_sync(0xffffffffu, mx0, 2));
        mx1 = fmaxf(mx1, __shfl_xor_sync(0xffffffffu, mx1, 1));
        mx1 = fmaxf(mx1, __shfl_xor_sync(0xffffffffu, mx1, 2));
        const float mn0 = fmaxf(m_lo, mx0);
        const float mn1 = fmaxf(m_hi, mx1);
        const float a0 = fexp(m_lo - mn0);
        const float a1 = fexp(m_hi - mn1);
        m_lo = mn0; m_hi = mn1;

        float sum0 = 0.f, sum1 = 0.f;
#pragma unroll
        for (int j = 0; j < 8; j++) {
            s[j][0] = fexp(s[j][0] - mn0);
            s[j][1] = fexp(s[j][1] - mn0);
            s[j][2] = fexp(s[j][2] - mn1);
            s[j][3] = fexp(s[j][3] - mn1);
            sum0 += s[j][0] + s[j][1];
            sum1 += s[j][2] + s[j][3];
        }
        sum0 += __shfl_xor_sync(0xffffffffu, sum0, 1);
        sum0 += __shfl_xor_sync(0xffffffffu, sum0, 2);
        sum1 += __shfl_xor_sync(0xffffffffu, sum1, 1);
        sum1 += __shfl_xor_sync(0xffffffffu, sum1, 2);
        l_lo = l_lo * a0 + sum0;
        l_hi = l_hi * a1 + sum1;
#pragma unroll
        for (int j = 0; j < 8; j++) {
            accO[j][0] *= a0; accO[j][1] *= a0;
            accO[j][2] *= a1; accO[j][3] *= a1;
        }

        // ---- O += P V (3-term) ----
        const uint32_t vbyt = (lane >> 4) * 16;
#pragma unroll
        for (int kc = 0; kc < 4; kc++) {
            uint32_t ph[4], pl[4];
            {
                const float p00 = s[2 * kc][0],     p01 = s[2 * kc][1];
                const float p02 = s[2 * kc][2],     p03 = s[2 * kc][3];
                const float p10 = s[2 * kc + 1][0], p11 = s[2 * kc + 1][1];
                const float p12 = s[2 * kc + 1][2], p13 = s[2 * kc + 1][3];
                ph[0] = packbf(p00, p01);
                ph[1] = packbf(p02, p03);
                ph[2] = packbf(p10, p11);
                ph[3] = packbf(p12, p13);
                pl[0] = packbf(p00 - __bfloat162float(__float2bfloat16_rn(p00)),
                               p01 - __bfloat162float(__float2bfloat16_rn(p01)));
                pl[1] = packbf(p02 - __bfloat162float(__float2bfloat16_rn(p02)),
                               p03 - __bfloat162float(__float2bfloat16_rn(p03)));
                pl[2] = packbf(p10 - __bfloat162float(__float2bfloat16_rn(p10)),
                               p11 - __bfloat162float(__float2bfloat16_rn(p11)));
                pl[3] = packbf(p12 - __bfloat162float(__float2bfloat16_rn(p12)),
                               p13 - __bfloat162float(__float2bfloat16_rn(p13)));
            }
            const uint32_t vrow = kc * 16 + (lane & 15);
#pragma unroll
            for (int np = 0; np < 4; np++) {
                const uint32_t vo = sb + vrow * LDS_B + np * 32 + vbyt;
                uint32_t vh[4], vl[4];
                ldsm_x4_t(vh, vo + V_HI);
                ldsm_x4_t(vl, vo + V_LO);
                mma16816(accO[np * 2 + 0], ph, vh[0], vh[1]);
                mma16816(accO[np * 2 + 1], ph, vh[2], vh[3]);
                mma16816(accO[np * 2 + 0], ph, vl[0], vl[1]);
                mma16816(accO[np * 2 + 1], ph, vl[2], vl[3]);
                mma16816(accO[np * 2 + 0], pl, vh[0], vh[1]);
                mma16816(accO[np * 2 + 1], pl, vh[2], vh[3]);
            }
        }
    }

    // ---- epilogue: normalize and write [B,S,D] ----
    const float il0 = 1.0f / l_lo;
    const float il1 = 1.0f / l_hi;
    const int b = bh >> 4, h = bh & 15;
    const int c_base = h * DKn + (lane & 3) * 2;
#pragma unroll
    for (int j = 0; j < 8; j++) {
        const int c = c_base + j * 8;
        float* d0 = g_A + ((size_t)(b * Sn + r_lo)) * Dn + c;
        float* d1 = g_A + ((size_t)(b * Sn + r_hi)) * Dn + c;
        d0[0] = accO[j][0] * il0; d0[1] = accO[j][1] * il0;
        d1[0] = accO[j][2] * il1; d1[1] = accO[j][3] * il1;
    }
}

// ---------------------------------------------------------------------------
extern "C" void kernel_launch(void* const* d_in, const int* in_sizes, int n_in,
                              void* d_out, int out_size)
{
    const float* k_in = (const float*)d_in[0];
    const float* q_in = (const float*)d_in[1];
    const float* v_in = (const float*)d_in[2];
    const float* w_q  = (const float*)d_in[3];
    const float* b_q  = (const float*)d_in[4];
    const float* w_k  = (const float*)d_in[5];
    const float* b_k  = (const float*)d_in[6];
    const float* w_v  = (const float*)d_in[7];
    const float* b_v  = (const float*)d_in[8];
    const float* w_o  = (const float*)d_in[9];
    const float* b_o  = (const float*)d_in[10];
    float* out = (float*)d_out;

    float *Qp, *Kp, *Vp, *Ap;
    cudaGetSymbolAddress((void**)&Qp, g_Q);
    cudaGetSymbolAddress((void**)&Kp, g_K);
    cudaGetSymbolAddress((void**)&Vp, g_V);
    cudaGetSymbolAddress((void**)&Ap, g_A);

    cudaFuncSetAttribute(gemm_tc, cudaFuncAttributeMaxDynamicSharedMemorySize,
                         GEMM_SMEM);

    const dim3 gg(32, 8);
    gemm_tc<<<gg, 256, GEMM_SMEM>>>(q_in, w_q, b_q, Qp, 1);
    gemm_tc<<<gg, 256, GEMM_SMEM>>>(k_in, w_k, b_k, Kp, 1);
    gemm_tc<<<gg, 256, GEMM_SMEM>>>(v_in, w_v, b_v, Vp, 1);

    attn_tc<<<dim3(16, 32), 256>>>();

    gemm_tc<<<gg, 256, GEMM_SMEM>>>(Ap, w_o, b_o, out, 0);
}

// round 7
// speedup vs baseline: 2.9035x; 1.1702x over previous
#include <cuda_runtime.h>
#include <cuda_bf16.h>
#include <cstdint>

#define Bn 2
#define Sn 2048
#define Dn 1024
#define Hn 16
#define DKn 64

#define NELEM (4096 * 1024)
#define WELEM (1024 * 1024)

// bf16 hi/lo scratch (device globals; no allocations allowed)
__device__ __nv_bfloat16 g_xqh[NELEM], g_xql[NELEM];
__device__ __nv_bfloat16 g_xkh[NELEM], g_xkl[NELEM];
__device__ __nv_bfloat16 g_xvh[NELEM], g_xvl[NELEM];
__device__ __nv_bfloat16 g_wqh[WELEM], g_wql[WELEM];
__device__ __nv_bfloat16 g_wkh[WELEM], g_wkl[WELEM];
__device__ __nv_bfloat16 g_wvh[WELEM], g_wvl[WELEM];
__device__ __nv_bfloat16 g_woh[WELEM], g_wol[WELEM];
__device__ __nv_bfloat16 g_Qh[NELEM], g_Ql[NELEM];   // [B,H,S,DK]
__device__ __nv_bfloat16 g_Kh[NELEM], g_Kl[NELEM];
__device__ __nv_bfloat16 g_Vh[NELEM], g_Vl[NELEM];
__device__ __nv_bfloat16 g_Ah[NELEM], g_Al[NELEM];   // [B,S,D]

// ---------------------------------------------------------------------------
// Helpers
// ---------------------------------------------------------------------------
__device__ __forceinline__ uint32_t smem_u32(const void* p) {
    uint32_t a;
    asm("{ .reg .u64 t; cvta.to.shared.u64 t, %1; cvt.u32.u64 %0, t; }"
        : "=r"(a) : "l"(p));
    return a;
}

__device__ __forceinline__ void ldsm_x4(uint32_t (&r)[4], uint32_t addr) {
    asm volatile("ldmatrix.sync.aligned.m8n8.x4.shared.b16 {%0,%1,%2,%3}, [%4];"
        : "=r"(r[0]), "=r"(r[1]), "=r"(r[2]), "=r"(r[3]) : "r"(addr));
}

__device__ __forceinline__ void ldsm_x4_t(uint32_t (&r)[4], uint32_t addr) {
    asm volatile("ldmatrix.sync.aligned.m8n8.x4.trans.shared.b16 {%0,%1,%2,%3}, [%4];"
        : "=r"(r[0]), "=r"(r[1]), "=r"(r[2]), "=r"(r[3]) : "r"(addr));
}

__device__ __forceinline__ void mma16816(float (&d)[4], const uint32_t (&a)[4],
                                         uint32_t b0, uint32_t b1) {
    asm volatile(
        "mma.sync.aligned.m16n8k16.row.col.f32.bf16.bf16.f32 "
        "{%0,%1,%2,%3}, {%4,%5,%6,%7}, {%8,%9}, {%0,%1,%2,%3};"
        : "+f"(d[0]), "+f"(d[1]), "+f"(d[2]), "+f"(d[3])
        : "r"(a[0]), "r"(a[1]), "r"(a[2]), "r"(a[3]), "r"(b0), "r"(b1));
}

#define CP_ASYNC16(dst, src) \
    asm volatile("cp.async.cg.shared.global [%0], [%1], 16;" \
                 :: "r"(dst), "l"(src) : "memory")
#define CP_COMMIT()  asm volatile("cp.async.commit_group;" ::: "memory")
#define CP_WAIT0()   asm volatile("cp.async.wait_group 0;" ::: "memory")
#define CP_WAIT1()   asm volatile("cp.async.wait_group 1;" ::: "memory")

__device__ __forceinline__ void split4(float4 v, uint2& hi, uint2& lo) {
    __nv_bfloat16 h0 = __float2bfloat16_rn(v.x);
    __nv_bfloat16 h1 = __float2bfloat16_rn(v.y);
    __nv_bfloat16 h2 = __float2bfloat16_rn(v.z);
    __nv_bfloat16 h3 = __float2bfloat16_rn(v.w);
    __nv_bfloat16 l0 = __float2bfloat16_rn(v.x - __bfloat162float(h0));
    __nv_bfloat16 l1 = __float2bfloat16_rn(v.y - __bfloat162float(h1));
    __nv_bfloat16 l2 = __float2bfloat16_rn(v.z - __bfloat162float(h2));
    __nv_bfloat16 l3 = __float2bfloat16_rn(v.w - __bfloat162float(h3));
    hi.x = ((uint32_t)__bfloat16_as_ushort(h1) << 16) | __bfloat16_as_ushort(h0);
    hi.y = ((uint32_t)__bfloat16_as_ushort(h3) << 16) | __bfloat16_as_ushort(h2);
    lo.x = ((uint32_t)__bfloat16_as_ushort(l1) << 16) | __bfloat16_as_ushort(l0);
    lo.y = ((uint32_t)__bfloat16_as_ushort(l3) << 16) | __bfloat16_as_ushort(l2);
}

__device__ __forceinline__ void split2(float a, float b, uint32_t& hi, uint32_t& lo) {
    __nv_bfloat16 ha = __float2bfloat16_rn(a);
    __nv_bfloat16 hb = __float2bfloat16_rn(b);
    __nv_bfloat16 la = __float2bfloat16_rn(a - __bfloat162float(ha));
    __nv_bfloat16 lb = __float2bfloat16_rn(b - __bfloat162float(hb));
    hi = ((uint32_t)__bfloat16_as_ushort(hb) << 16) | __bfloat16_as_ushort(ha);
    lo = ((uint32_t)__bfloat16_as_ushort(lb) << 16) | __bfloat16_as_ushort(la);
}

__device__ __forceinline__ uint32_t packbf(float a, float b) {
    return ((uint32_t)__bfloat16_as_ushort(__float2bfloat16_rn(b)) << 16) |
           __bfloat16_as_ushort(__float2bfloat16_rn(a));
}

// Fast exp on the FMA pipe (no MUFU). Valid for x <= 0.
__device__ __forceinline__ float fexp(float x) {
    x = fmaxf(x, -80.0f);
    float n = rintf(x * 1.4426950408889634f);
    float r = fmaf(n, -0.693359375f, x);
    r = fmaf(n, 2.12194440e-4f, r);
    float p = fmaf(r, 8.3333333e-3f, 4.1666667e-2f);
    p = fmaf(r, p, 1.6666667e-1f);
    p = fmaf(r, p, 0.5f);
    p = fmaf(r, p, 1.0f);
    p = fmaf(r, p, 1.0f);
    int e = ((int)n + 127) << 23;
    return p * __int_as_float(e);
}

// ---------------------------------------------------------------------------
// Prepass: fp32 -> bf16 hi/lo split
// ---------------------------------------------------------------------------
__global__ __launch_bounds__(256) void conv_split(
    const float* __restrict__ x,
    __nv_bfloat16* __restrict__ hi,
    __nv_bfloat16* __restrict__ lo, int n4)
{
    const int i = blockIdx.x * 256 + threadIdx.x;
    if (i < n4) {
        float4 v = ((const float4*)x)[i];
        uint2 h, l;
        split4(v, h, l);
        ((uint2*)hi)[i] = h;
        ((uint2*)lo)[i] = l;
    }
}

// ---------------------------------------------------------------------------
// bf16 HMMA GEMM, 3-term split, cp.async 3-stage pipeline.
// Y[m,n] = sum_k X[m,k]*W[n,k] + bias[n].  M=4096, N=K=1024.
// Tile 128x128, BK=32, 256 threads, 8 warps 4(M)x2(N).
// mode 1: bf16 hi/lo permuted [B,H,S,DK] out; mode 0: fp32 row-major out.
// ---------------------------------------------------------------------------
#define LDA_S   80
#define MAT_SZ  (128 * LDA_S)            // 10240
#define STG_SZ  (4 * MAT_SZ)             // 40960
#define GEMM_SMEM (3 * STG_SZ)           // 122880

__global__ __launch_bounds__(256, 1) void gemm_bf16(
    const __nv_bfloat16* __restrict__ Xh, const __nv_bfloat16* __restrict__ Xl,
    const __nv_bfloat16* __restrict__ Wh, const __nv_bfloat16* __restrict__ Wl,
    const float* __restrict__ bias,
    float* __restrict__ Yf,
    __nv_bfloat16* __restrict__ Yh, __nv_bfloat16* __restrict__ Yl,
    int mode)
{
    extern __shared__ char sm[];
    const uint32_t sb = smem_u32(sm);
    const int tid  = threadIdx.x;
    const int lane = tid & 31;
    const int wid  = tid >> 5;
    const int wm   = wid >> 1;
    const int wn   = wid & 1;

    const int m0 = blockIdx.x * 128;
    const int n0 = blockIdx.y * 128;
    const __nv_bfloat16* src[4] = {
        Xh + (size_t)m0 * Dn, Xl + (size_t)m0 * Dn,
        Wh + (size_t)n0 * Dn, Wl + (size_t)n0 * Dn };

    // chunk mapping: per matrix 512 16B-chunks (128 rows x 4), 2 per thread
    const int cr0 = (tid + 0)   >> 2;
    const int cc0 = (tid & 3)   * 16;
    const int cr1 = (tid + 256) >> 2;

    const uint32_t a_row = wm * 32 + (lane & 15);
    const uint32_t a_byt = (lane >> 4) * 16;
    const uint32_t b_row = wn * 64 + (lane & 7) + ((lane >> 4) << 3);
    const uint32_t b_byt = ((lane >> 3) & 1) * 16;

    float acc[2][8][4];
#pragma unroll
    for (int i = 0; i < 2; i++)
#pragma unroll
        for (int j = 0; j < 8; j++)
#pragma unroll
            for (int k = 0; k < 4; k++) acc[i][j][k] = 0.f;

    // prologue: stages 0,1
#pragma unroll
    for (int ps = 0; ps < 2; ps++) {
        const uint32_t st = sb + ps * STG_SZ;
#pragma unroll
        for (int mt = 0; mt < 4; mt++) {
            CP_ASYNC16(st + mt * MAT_SZ + cr0 * LDA_S + cc0,
                       src[mt] + (size_t)cr0 * Dn + ps * 32 + (cc0 >> 1));
            CP_ASYNC16(st + mt * MAT_SZ + cr1 * LDA_S + cc0,
                       src[mt] + (size_t)cr1 * Dn + ps * 32 + (cc0 >> 1));
        }
        CP_COMMIT();
    }

#pragma unroll 1
    for (int s = 0; s < 32; s++) {
        CP_WAIT1();
        __syncthreads();

        const uint32_t stg = sb + (s % 3) * STG_SZ;
#pragma unroll
        for (int ks = 0; ks < 2; ks++) {
            uint32_t ah[2][4], al[2][4], bh[4][4], bl[4][4];
#pragma unroll
            for (int mf = 0; mf < 2; mf++) {
                const uint32_t ao = stg + (a_row + mf * 16) * LDA_S + ks * 32 + a_byt;
                ldsm_x4(ah[mf], ao);
                ldsm_x4(al[mf], ao + MAT_SZ);
            }
#pragma unroll
            for (int nq = 0; nq < 4; nq++) {
                const uint32_t bo = stg + 2 * MAT_SZ +
                                    (b_row + nq * 16) * LDA_S + ks * 32 + b_byt;
                ldsm_x4(bh[nq], bo);
                ldsm_x4(bl[nq], bo + MAT_SZ);
            }
#pragma unroll
            for (int mf = 0; mf < 2; mf++)
#pragma unroll
                for (int nq = 0; nq < 4; nq++) {
                    mma16816(acc[mf][nq * 2 + 0], ah[mf], bh[nq][0], bh[nq][1]);
                    mma16816(acc[mf][nq * 2 + 1], ah[mf], bh[nq][2], bh[nq][3]);
                    mma16816(acc[mf][nq * 2 + 0], ah[mf], bl[nq][0], bl[nq][1]);
                    mma16816(acc[mf][nq * 2 + 1], ah[mf], bl[nq][2], bl[nq][3]);
                    mma16816(acc[mf][nq * 2 + 0], al[mf], bh[nq][0], bh[nq][1]);
                    mma16816(acc[mf][nq * 2 + 1], al[mf], bh[nq][2], bh[nq][3]);
                }
        }

        if (s + 2 < 32) {
            const uint32_t st = sb + ((s + 2) % 3) * STG_SZ;
            const int k8 = (s + 2) * 32 + (cc0 >> 1);
#pragma unroll
            for (int mt = 0; mt < 4; mt++) {
                CP_ASYNC16(st + mt * MAT_SZ + cr0 * LDA_S + cc0,
                           src[mt] + (size_t)cr0 * Dn + k8);
                CP_ASYNC16(st + mt * MAT_SZ + cr1 * LDA_S + cc0,
                           src[mt] + (size_t)cr1 * Dn + k8);
            }
        }
        CP_COMMIT();
    }

    // Epilogue
#pragma unroll
    for (int mf = 0; mf < 2; mf++) {
        const int mr = m0 + wm * 32 + mf * 16 + (lane >> 2);
#pragma unroll
        for (int nf = 0; nf < 8; nf++) {
            const int c0 = n0 + wn * 64 + nf * 8 + (lane & 3) * 2;
            const float b0 = bias[c0], b1 = bias[c0 + 1];
#pragma unroll
            for (int rr = 0; rr < 2; rr++) {
                const int m = mr + rr * 8;
                const float v0 = acc[mf][nf][rr * 2 + 0] + b0;
                const float v1 = acc[mf][nf][rr * 2 + 1] + b1;
                if (mode) {
                    const int b = m >> 11, srow = m & (Sn - 1);
                    const int h = c0 >> 6, dk = c0 & 63;
                    const size_t idx =
                        (((size_t)(b * Hn + h)) * Sn + srow) * DKn + dk;
                    uint32_t hi, lo;
                    split2(v0, v1, hi, lo);
                    *(uint32_t*)(Yh + idx) = hi;
                    *(uint32_t*)(Yl + idx) = lo;
                } else {
                    float* dst = Yf + (size_t)m * Dn + c0;
                    dst[0] = v0; dst[1] = v1;
                }
            }
        }
    }
}

// ---------------------------------------------------------------------------
// HMMA causal flash attention, bf16 hi/lo inputs, cp.async double-buffered KV.
// 128 q-rows per CTA (8 warps x 16 rows), KV tiles of 64.
// ---------------------------------------------------------------------------
#define LDS_B   144
#define QMAT    18432                  // 128 * 144
#define KVMAT   9216                   // 64 * 144
#define KV_STG  (4 * KVMAT)            // 36864: Kh,Kl,Vh,Vl
#define ATTN_SMEM (2 * KV_STG)         // 73728 (Q staged in buf1, then reused)

__global__ __launch_bounds__(256) void attn_tc()
{
    extern __shared__ char smem[];
    const uint32_t sb = smem_u32(smem);
    const int tid = threadIdx.x, lane = tid & 31, wid = tid >> 5;

    const int qt = 15 - blockIdx.x;       // heavy blocks first
    const int bh = blockIdx.y;
    const int q0 = qt * 128;

    const size_t base = (size_t)bh * Sn * DKn;
    const __nv_bfloat16* Qh = g_Qh + base;
    const __nv_bfloat16* Ql = g_Ql + base;
    const __nv_bfloat16* Kh = g_Kh + base;
    const __nv_bfloat16* Kl = g_Kl + base;
    const __nv_bfloat16* Vh = g_Vh + base;
    const __nv_bfloat16* Vl = g_Vl + base;

    // ---- stage Q (bf16 hi/lo) into buf1, then pull into A-frags ----
    {
        char* qhd = smem + KV_STG;           // hi
        char* qld = smem + KV_STG + QMAT;    // lo
#pragma unroll
        for (int i = 0; i < 4; i++) {
            const int c = tid + i * 256;     // 1024 chunks of 16B
            const int row = c >> 3, ch = c & 7;
            const uint32_t off = row * LDS_B + ch * 16;
            *(uint4*)(qhd + off) =
                *(const uint4*)(Qh + (size_t)(q0 + row) * DKn + ch * 8);
            *(uint4*)(qld + off) =
                *(const uint4*)(Ql + (size_t)(q0 + row) * DKn + ch * 8);
        }
    }
    __syncthreads();

    uint32_t qfh[4][4], qfl[4][4];
    {
        const uint32_t arow = wid * 16 + (lane & 15);
        const uint32_t abyt = (lane >> 4) * 16;
#pragma unroll
        for (int kc = 0; kc < 4; kc++) {
            const uint32_t ao = sb + KV_STG + arow * LDS_B + kc * 32 + abyt;
            ldsm_x4(qfh[kc], ao);
            ldsm_x4(qfl[kc], ao + QMAT);
        }
    }

    float accO[8][4];
#pragma unroll
    for (int j = 0; j < 8; j++)
#pragma unroll
        for (int k = 0; k < 4; k++) accO[j][k] = 0.f;
    float m_lo = -1e30f, m_hi = -1e30f, l_lo = 0.f, l_hi = 0.f;

    const int r_lo = q0 + wid * 16 + (lane >> 2);
    const int r_hi = r_lo + 8;
    const uint32_t brow = (lane & 7) + ((lane >> 4) << 3);
    const uint32_t bbyt = ((lane >> 3) & 1) * 16;
    const uint32_t vbyt = (lane >> 4) * 16;

    const int ntiles = 2 * qt + 2;

    // KV tile loader: 64 rows x 8 chunks (16B) per matrix = 512 chunks;
    // 256 threads x 2 rows each (lr, lr+32), full 128-byte rows.
    const int lr = tid >> 3;              // 0..31
    const int lc = (tid & 7) * 16;        // byte offset within row (0..112)
    const int le = lc >> 1;               // bf16 element offset

    // prologue: tile 0 -> buf 0
    {
        const uint32_t st = sb;
#pragma unroll
        for (int rr = 0; rr < 2; rr++) {
            const int row = lr + rr * 32;
            const uint32_t so = row * LDS_B + lc;
            const size_t go = (size_t)row * DKn + le;
            CP_ASYNC16(st + 0 * KVMAT + so, Kh + go);
            CP_ASYNC16(st + 1 * KVMAT + so, Kl + go);
            CP_ASYNC16(st + 2 * KVMAT + so, Vh + go);
            CP_ASYNC16(st + 3 * KVMAT + so, Vl + go);
        }
        CP_COMMIT();
    }

#pragma unroll 1
    for (int kt = 0; kt < ntiles; kt++) {
        CP_WAIT0();
        __syncthreads();

        // issue next tile into the other buffer (overlaps with compute below)
        if (kt + 1 < ntiles) {
            const uint32_t st = sb + ((kt + 1) & 1) * KV_STG;
#pragma unroll
            for (int rr = 0; rr < 2; rr++) {
                const int row = lr + rr * 32;
                const uint32_t so = row * LDS_B + lc;
                const size_t go = (size_t)((kt + 1) * 64 + row) * DKn + le;
                CP_ASYNC16(st + 0 * KVMAT + so, Kh + go);
                CP_ASYNC16(st + 1 * KVMAT + so, Kl + go);
                CP_ASYNC16(st + 2 * KVMAT + so, Vh + go);
                CP_ASYNC16(st + 3 * KVMAT + so, Vl + go);
            }
        }
        CP_COMMIT();

        const uint32_t stg = sb + (kt & 1) * KV_STG;
        const int k0 = kt * 64;

        // ---- S = Q K^T (3-term) ----
        float s[8][4];
#pragma unroll
        for (int j = 0; j < 8; j++)
#pragma unroll
            for (int k = 0; k < 4; k++) s[j][k] = 0.f;

#pragma unroll
        for (int kc = 0; kc < 4; kc++) {
#pragma unroll
            for (int nq = 0; nq < 4; nq++) {
                const uint32_t bo = stg + (brow + nq * 16) * LDS_B + kc * 32 + bbyt;
                uint32_t kh[4], kl[4];
                ldsm_x4(kh, bo);
                ldsm_x4(kl, bo + KVMAT);
                mma16816(s[nq * 2 + 0], qfh[kc], kh[0], kh[1]);
                mma16816(s[nq * 2 + 1], qfh[kc], kh[2], kh[3]);
                mma16816(s[nq * 2 + 0], qfh[kc], kl[0], kl[1]);
                mma16816(s[nq * 2 + 1], qfh[kc], kl[2], kl[3]);
                mma16816(s[nq * 2 + 0], qfl[kc], kh[0], kh[1]);
                mma16816(s[nq * 2 + 1], qfl[kc], kh[2], kh[3]);
            }
        }

        // ---- scale + causal mask ----
        const bool need_mask = (k0 + 63) > r_lo;
#pragma unroll
        for (int j = 0; j < 8; j++) {
            const int c = k0 + j * 8 + (lane & 3) * 2;
            s[j][0] *= 0.125f; s[j][1] *= 0.125f;
            s[j][2] *= 0.125f; s[j][3] *= 0.125f;
            if (need_mask) {
                if (c > r_lo)     s[j][0] = -1e30f;
                if (c + 1 > r_lo) s[j][1] = -1e30f;
                if (c > r_hi)     s[j][2] = -1e30f;
                if (c + 1 > r_hi) s[j][3] = -1e30f;
            }
        }

        // ---- online softmax ----
        float mx0 = -1e30f, mx1 = -1e30f;
#pragma unroll
        for (int j = 0; j < 8; j++) {
            mx0 = fmaxf(mx0, fmaxf(s[j][0], s[j][1]));
            mx1 = fmaxf(mx1, fmaxf(s[j][2], s[j][3]));
        }
        mx0 = fmaxf(mx0, __shfl_xor_sync(0xffffffffu, mx0, 1));
        mx0 = fmaxf(mx0, __shfl_xor_sync(0xffffffffu, mx0, 2));
        mx1 = fmaxf(mx1, __shfl_xor_sync(0xffffffffu, mx1, 1));
        mx1 = fmaxf(mx1, __shfl_xor_sync(0xffffffffu, mx1, 2));
        const float mn0 = fmaxf(m_lo, mx0);
        const float mn1 = fmaxf(m_hi, mx1);
        const float a0 = fexp(m_lo - mn0);
        const float a1 = fexp(m_hi - mn1);
        m_lo = mn0; m_hi = mn1;

        float sum0 = 0.f, sum1 = 0.f;
#pragma unroll
        for (int j = 0; j < 8; j++) {
            s[j][0] = fexp(s[j][0] - mn0);
            s[j][1] = fexp(s[j][1] - mn0);
            s[j][2] = fexp(s[j][2] - mn1);
            s[j][3] = fexp(s[j][3] - mn1);
            sum0 += s[j][0] + s[j][1];
            sum1 += s[j][2] + s[j][3];
        }
        sum0 += __shfl_xor_sync(0xffffffffu, sum0, 1);
        sum0 += __shfl_xor_sync(0xffffffffu, sum0, 2);
        sum1 += __shfl_xor_sync(0xffffffffu, sum1, 1);
        sum1 += __shfl_xor_sync(0xffffffffu, sum1, 2);
        l_lo = l_lo * a0 + sum0;
        l_hi = l_hi * a1 + sum1;
#pragma unroll
        for (int j = 0; j < 8; j++) {
            accO[j][0] *= a0; accO[j][1] *= a0;
            accO[j][2] *= a1; accO[j][3] *= a1;
        }

        // ---- O += P V (3-term) ----
#pragma unroll
        for (int kc = 0; kc < 4; kc++) {
            uint32_t ph[4], pl[4];
            {
                const float p00 = s[2 * kc][0],     p01 = s[2 * kc][1];
                const float p02 = s[2 * kc][2],     p03 = s[2 * kc][3];
                const float p10 = s[2 * kc + 1][0], p11 = s[2 * kc + 1][1];
                const float p12 = s[2 * kc + 1][2], p13 = s[2 * kc + 1][3];
                ph[0] = packbf(p00, p01);
                ph[1] = packbf(p02, p03);
                ph[2] = packbf(p10, p11);
                ph[3] = packbf(p12, p13);
                pl[0] = packbf(p00 - __bfloat162float(__float2bfloat16_rn(p00)),
                               p01 - __bfloat162float(__float2bfloat16_rn(p01)));
                pl[1] = packbf(p02 - __bfloat162float(__float2bfloat16_rn(p02)),
                               p03 - __bfloat162float(__float2bfloat16_rn(p03)));
                pl[2] = packbf(p10 - __bfloat162float(__float2bfloat16_rn(p10)),
                               p11 - __bfloat162float(__float2bfloat16_rn(p11)));
                pl[3] = packbf(p12 - __bfloat162float(__float2bfloat16_rn(p12)),
                               p13 - __bfloat162float(__float2bfloat16_rn(p13)));
            }
            const uint32_t vrow = kc * 16 + (lane & 15);
#pragma unroll
            for (int np = 0; np < 4; np++) {
                const uint32_t vo = stg + 2 * KVMAT + vrow * LDS_B + np * 32 + vbyt;
                uint32_t vh[4], vl[4];
                ldsm_x4_t(vh, vo);
                ldsm_x4_t(vl, vo + KVMAT);
                mma16816(accO[np * 2 + 0], ph, vh[0], vh[1]);
                mma16816(accO[np * 2 + 1], ph, vh[2], vh[3]);
                mma16816(accO[np * 2 + 0], ph, vl[0], vl[1]);
                mma16816(accO[np * 2 + 1], ph, vl[2], vl[3]);
                mma16816(accO[np * 2 + 0], pl, vh[0], vh[1]);
                mma16816(accO[np * 2 + 1], pl, vh[2], vh[3]);
            }
        }
    }

    // ---- epilogue: normalize, split to bf16 hi/lo, write [B,S,D] ----
    const float il0 = 1.0f / l_lo;
    const float il1 = 1.0f / l_hi;
    const int b = bh >> 4, h = bh & 15;
    const int c_base = h * DKn + (lane & 3) * 2;
#pragma unroll
    for (int j = 0; j < 8; j++) {
        const int c = c_base + j * 8;
        const size_t i0 = ((size_t)(b * Sn + r_lo)) * Dn + c;
        const size_t i1 = ((size_t)(b * Sn + r_hi)) * Dn + c;
        uint32_t hi, lo;
        split2(accO[j][0] * il0, accO[j][1] * il0, hi, lo);
        *(uint32_t*)(g_Ah + i0) = hi;
        *(uint32_t*)(g_Al + i0) = lo;
        split2(accO[j][2] * il1, accO[j][3] * il1, hi, lo);
        *(uint32_t*)(g_Ah + i1) = hi;
        *(uint32_t*)(g_Al + i1) = lo;
    }
}

// ---------------------------------------------------------------------------
extern "C" void kernel_launch(void* const* d_in, const int* in_sizes, int n_in,
                              void* d_out, int out_size)
{
    const float* k_in = (const float*)d_in[0];
    const float* q_in = (const float*)d_in[1];
    const float* v_in = (const float*)d_in[2];
    const float* w_q  = (const float*)d_in[3];
    const float* b_q  = (const float*)d_in[4];
    const float* w_k  = (const float*)d_in[5];
    const float* b_k  = (const float*)d_in[6];
    const float* w_v  = (const float*)d_in[7];
    const float* b_v  = (const float*)d_in[8];
    const float* w_o  = (const float*)d_in[9];
    const float* b_o  = (const float*)d_in[10];
    float* out = (float*)d_out;

    // resolve scratch symbols
    __nv_bfloat16 *xqh, *xql, *xkh, *xkl, *xvh, *xvl;
    __nv_bfloat16 *wqh, *wql, *wkh, *wkl, *wvh, *wvl, *woh, *wol;
    __nv_bfloat16 *Qh, *Ql, *Kh, *Kl, *Vh, *Vl, *Ah, *Al;
    cudaGetSymbolAddress((void**)&xqh, g_xqh); cudaGetSymbolAddress((void**)&xql, g_xql);
    cudaGetSymbolAddress((void**)&xkh, g_xkh); cudaGetSymbolAddress((void**)&xkl, g_xkl);
    cudaGetSymbolAddress((void**)&xvh, g_xvh); cudaGetSymbolAddress((void**)&xvl, g_xvl);
    cudaGetSymbolAddress((void**)&wqh, g_wqh); cudaGetSymbolAddress((void**)&wql, g_wql);
    cudaGetSymbolAddress((void**)&wkh, g_wkh); cudaGetSymbolAddress((void**)&wkl, g_wkl);
    cudaGetSymbolAddress((void**)&wvh, g_wvh); cudaGetSymbolAddress((void**)&wvl, g_wvl);
    cudaGetSymbolAddress((void**)&woh, g_woh); cudaGetSymbolAddress((void**)&wol, g_wol);
    cudaGetSymbolAddress((void**)&Qh, g_Qh);   cudaGetSymbolAddress((void**)&Ql, g_Ql);
    cudaGetSymbolAddress((void**)&Kh, g_Kh);   cudaGetSymbolAddress((void**)&Kl, g_Kl);
    cudaGetSymbolAddress((void**)&Vh, g_Vh);   cudaGetSymbolAddress((void**)&Vl, g_Vl);
    cudaGetSymbolAddress((void**)&Ah, g_Ah);   cudaGetSymbolAddress((void**)&Al, g_Al);

    cudaFuncSetAttribute(gemm_bf16, cudaFuncAttributeMaxDynamicSharedMemorySize,
                         GEMM_SMEM);
    cudaFuncSetAttribute(attn_tc, cudaFuncAttributeMaxDynamicSharedMemorySize,
                         ATTN_SMEM);

    // prepass conversions
    conv_split<<<4096, 256>>>(q_in, xqh, xql, NELEM / 4);
    conv_split<<<4096, 256>>>(k_in, xkh, xkl, NELEM / 4);
    conv_split<<<4096, 256>>>(v_in, xvh, xvl, NELEM / 4);
    conv_split<<<1024, 256>>>(w_q, wqh, wql, WELEM / 4);
    conv_split<<<1024, 256>>>(w_k, wkh, wkl, WELEM / 4);
    conv_split<<<1024, 256>>>(w_v, wvh, wvl, WELEM / 4);
    conv_split<<<1024, 256>>>(w_o, woh, wol, WELEM / 4);

    const dim3 gg(32, 8);
    gemm_bf16<<<gg, 256, GEMM_SMEM>>>(xqh, xql, wqh, wql, b_q, nullptr, Qh, Ql, 1);
    gemm_bf16<<<gg, 256, GEMM_SMEM>>>(xkh, xkl, wkh, wkl, b_k, nullptr, Kh, Kl, 1);
    gemm_bf16<<<gg, 256, GEMM_SMEM>>>(xvh, xvl, wvh, wvl, b_v, nullptr, Vh, Vl, 1);

    attn_tc<<<dim3(16, 32), 256, ATTN_SMEM>>>();

    gemm_bf16<<<gg, 256, GEMM_SMEM>>>(Ah, Al, woh, wol, b_o, out, nullptr, nullptr, 0);
}

// round 8
// speedup vs baseline: 3.1010x; 1.0680x over previous
#include <cuda_runtime.h>
#include <cuda_bf16.h>
#include <cstdint>

#define Bn 2
#define Sn 2048
#define Dn 1024
#define Hn 16
#define DKn 64

#define NELEM (4096 * 1024)
#define WELEM (1024 * 1024)

// bf16 hi/lo scratch (device globals; no allocations allowed)
__device__ __nv_bfloat16 g_xqh[NELEM], g_xql[NELEM];
__device__ __nv_bfloat16 g_xkh[NELEM], g_xkl[NELEM];
__device__ __nv_bfloat16 g_xvh[NELEM], g_xvl[NELEM];
__device__ __nv_bfloat16 g_wqh[WELEM], g_wql[WELEM];
__device__ __nv_bfloat16 g_wkh[WELEM], g_wkl[WELEM];
__device__ __nv_bfloat16 g_wvh[WELEM], g_wvl[WELEM];
__device__ __nv_bfloat16 g_woh[WELEM], g_wol[WELEM];
__device__ __nv_bfloat16 g_Qh[NELEM], g_Ql[NELEM];   // [B,H,S,DK] (pre-scaled)
__device__ __nv_bfloat16 g_Kh[NELEM], g_Kl[NELEM];
__device__ __nv_bfloat16 g_Vh[NELEM], g_Vl[NELEM];
__device__ __nv_bfloat16 g_Ah[NELEM], g_Al[NELEM];   // [B,S,D]

// ---------------------------------------------------------------------------
// Helpers
// ---------------------------------------------------------------------------
__device__ __forceinline__ uint32_t smem_u32(const void* p) {
    uint32_t a;
    asm("{ .reg .u64 t; cvta.to.shared.u64 t, %1; cvt.u32.u64 %0, t; }"
        : "=r"(a) : "l"(p));
    return a;
}

__device__ __forceinline__ void ldsm_x4(uint32_t (&r)[4], uint32_t addr) {
    asm volatile("ldmatrix.sync.aligned.m8n8.x4.shared.b16 {%0,%1,%2,%3}, [%4];"
        : "=r"(r[0]), "=r"(r[1]), "=r"(r[2]), "=r"(r[3]) : "r"(addr));
}

__device__ __forceinline__ void ldsm_x4_t(uint32_t (&r)[4], uint32_t addr) {
    asm volatile("ldmatrix.sync.aligned.m8n8.x4.trans.shared.b16 {%0,%1,%2,%3}, [%4];"
        : "=r"(r[0]), "=r"(r[1]), "=r"(r[2]), "=r"(r[3]) : "r"(addr));
}

__device__ __forceinline__ void mma16816(float (&d)[4], const uint32_t (&a)[4],
                                         uint32_t b0, uint32_t b1) {
    asm volatile(
        "mma.sync.aligned.m16n8k16.row.col.f32.bf16.bf16.f32 "
        "{%0,%1,%2,%3}, {%4,%5,%6,%7}, {%8,%9}, {%0,%1,%2,%3};"
        : "+f"(d[0]), "+f"(d[1]), "+f"(d[2]), "+f"(d[3])
        : "r"(a[0]), "r"(a[1]), "r"(a[2]), "r"(a[3]), "r"(b0), "r"(b1));
}

#define CP_ASYNC16(dst, src) \
    asm volatile("cp.async.cg.shared.global [%0], [%1], 16;" \
                 :: "r"(dst), "l"(src) : "memory")
#define CP_COMMIT()  asm volatile("cp.async.commit_group;" ::: "memory")
#define CP_WAIT0()   asm volatile("cp.async.wait_group 0;" ::: "memory")
#define CP_WAIT1()   asm volatile("cp.async.wait_group 1;" ::: "memory")

__device__ __forceinline__ void split4(float4 v, uint2& hi, uint2& lo) {
    __nv_bfloat16 h0 = __float2bfloat16_rn(v.x);
    __nv_bfloat16 h1 = __float2bfloat16_rn(v.y);
    __nv_bfloat16 h2 = __float2bfloat16_rn(v.z);
    __nv_bfloat16 h3 = __float2bfloat16_rn(v.w);
    __nv_bfloat16 l0 = __float2bfloat16_rn(v.x - __bfloat162float(h0));
    __nv_bfloat16 l1 = __float2bfloat16_rn(v.y - __bfloat162float(h1));
    __nv_bfloat16 l2 = __float2bfloat16_rn(v.z - __bfloat162float(h2));
    __nv_bfloat16 l3 = __float2bfloat16_rn(v.w - __bfloat162float(h3));
    hi.x = ((uint32_t)__bfloat16_as_ushort(h1) << 16) | __bfloat16_as_ushort(h0);
    hi.y = ((uint32_t)__bfloat16_as_ushort(h3) << 16) | __bfloat16_as_ushort(h2);
    lo.x = ((uint32_t)__bfloat16_as_ushort(l1) << 16) | __bfloat16_as_ushort(l0);
    lo.y = ((uint32_t)__bfloat16_as_ushort(l3) << 16) | __bfloat16_as_ushort(l2);
}

__device__ __forceinline__ void split2(float a, float b, uint32_t& hi, uint32_t& lo) {
    __nv_bfloat16 ha = __float2bfloat16_rn(a);
    __nv_bfloat16 hb = __float2bfloat16_rn(b);
    __nv_bfloat16 la = __float2bfloat16_rn(a - __bfloat162float(ha));
    __nv_bfloat16 lb = __float2bfloat16_rn(b - __bfloat162float(hb));
    hi = ((uint32_t)__bfloat16_as_ushort(hb) << 16) | __bfloat16_as_ushort(ha);
    lo = ((uint32_t)__bfloat16_as_ushort(lb) << 16) | __bfloat16_as_ushort(la);
}

__device__ __forceinline__ uint32_t packbf(float a, float b) {
    return ((uint32_t)__bfloat16_as_ushort(__float2bfloat16_rn(b)) << 16) |
           __bfloat16_as_ushort(__float2bfloat16_rn(a));
}

// Fast 2^x on the FMA pipe. Valid for x <= 0 (clamped at -126). |err|~2.4e-6.
__device__ __forceinline__ float fexp2(float x) {
    x = fmaxf(x, -126.0f);
    float n = rintf(x);
    float r = x - n;                       // exact, r in [-0.5, 0.5]
    float p = fmaf(r, 1.3333558e-3f, 9.6181291e-3f);
    p = fmaf(r, p, 5.5504109e-2f);
    p = fmaf(r, p, 2.4022651e-1f);
    p = fmaf(r, p, 6.9314718e-1f);
    p = fmaf(r, p, 1.0f);
    int e = ((int)n + 127) << 23;
    return p * __int_as_float(e);
}

// ---------------------------------------------------------------------------
// Prepass: fp32 -> bf16 hi/lo split for all 7 tensors in ONE launch.
// grid = (1024, 7); z selects tensor; 4 float4 per thread, warp-coalesced.
// ---------------------------------------------------------------------------
__global__ __launch_bounds__(256) void conv_all(
    const float* __restrict__ q, const float* __restrict__ k,
    const float* __restrict__ v,
    const float* __restrict__ wq, const float* __restrict__ wk,
    const float* __restrict__ wv, const float* __restrict__ wo,
    __nv_bfloat16* qh, __nv_bfloat16* ql,
    __nv_bfloat16* kh, __nv_bfloat16* kl,
    __nv_bfloat16* vh, __nv_bfloat16* vl,
    __nv_bfloat16* wqh, __nv_bfloat16* wql,
    __nv_bfloat16* wkh, __nv_bfloat16* wkl,
    __nv_bfloat16* wvh, __nv_bfloat16* wvl,
    __nv_bfloat16* woh, __nv_bfloat16* wol)
{
    const int z = blockIdx.y;
    const float* src;
    __nv_bfloat16 *H, *L;
    int n4;
    switch (z) {
        case 0: src = q;  H = qh;  L = ql;  n4 = NELEM / 4; break;
        case 1: src = k;  H = kh;  L = kl;  n4 = NELEM / 4; break;
        case 2: src = v;  H = vh;  L = vl;  n4 = NELEM / 4; break;
        case 3: src = wq; H = wqh; L = wql; n4 = WELEM / 4; break;
        case 4: src = wk; H = wkh; L = wkl; n4 = WELEM / 4; break;
        case 5: src = wv; H = wvh; L = wvl; n4 = WELEM / 4; break;
        default: src = wo; H = woh; L = wol; n4 = WELEM / 4; break;
    }
    const int base = blockIdx.x * 1024 + threadIdx.x;
    if (base >= n4) return;
#pragma unroll
    for (int u = 0; u < 4; u++) {
        const int i = base + u * 256;
        if (i < n4) {
            float4 vv = ((const float4*)src)[i];
            uint2 h, l;
            split4(vv, h, l);
            ((uint2*)H)[i] = h;
            ((uint2*)L)[i] = l;
        }
    }
}

// ---------------------------------------------------------------------------
// bf16 HMMA GEMM body, 3-term split, cp.async 3-stage pipeline.
// Tile 128x128, BK=32, 256 threads, 8 warps 4(M)x2(N).
// MODE 1: bf16 hi/lo permuted [B,H,S,DK] out (scaled); MODE 0: fp32 out.
// ---------------------------------------------------------------------------
#define LDA_S   80
#define MAT_SZ  (128 * LDA_S)            // 10240
#define STG_SZ  (4 * MAT_SZ)             // 40960
#define GEMM_SMEM (3 * STG_SZ)           // 122880

struct GemmJob {
    const __nv_bfloat16 *Xh, *Xl, *Wh, *Wl;
    const float* bias;
    __nv_bfloat16 *Yh, *Yl;
    float oscale;
};

template <int MODE>
__device__ __forceinline__ void gemm_body(
    const __nv_bfloat16* __restrict__ Xh, const __nv_bfloat16* __restrict__ Xl,
    const __nv_bfloat16* __restrict__ Wh, const __nv_bfloat16* __restrict__ Wl,
    const float* __restrict__ bias,
    float* __restrict__ Yf,
    __nv_bfloat16* __restrict__ Yh, __nv_bfloat16* __restrict__ Yl,
    float oscale, char* sm)
{
    const uint32_t sb = smem_u32(sm);
    const int tid  = threadIdx.x;
    const int lane = tid & 31;
    const int wid  = tid >> 5;
    const int wm   = wid >> 1;
    const int wn   = wid & 1;

    const int m0 = blockIdx.x * 128;
    const int n0 = blockIdx.y * 128;
    const __nv_bfloat16* src[4] = {
        Xh + (size_t)m0 * Dn, Xl + (size_t)m0 * Dn,
        Wh + (size_t)n0 * Dn, Wl + (size_t)n0 * Dn };

    const int cr0 = (tid + 0)   >> 2;
    const int cc0 = (tid & 3)   * 16;
    const int cr1 = (tid + 256) >> 2;

    const uint32_t a_row = wm * 32 + (lane & 15);
    const uint32_t a_byt = (lane >> 4) * 16;
    const uint32_t b_row = wn * 64 + (lane & 7) + ((lane >> 4) << 3);
    const uint32_t b_byt = ((lane >> 3) & 1) * 16;

    float acc[2][8][4];
#pragma unroll
    for (int i = 0; i < 2; i++)
#pragma unroll
        for (int j = 0; j < 8; j++)
#pragma unroll
            for (int k = 0; k < 4; k++) acc[i][j][k] = 0.f;

#pragma unroll
    for (int ps = 0; ps < 2; ps++) {
        const uint32_t st = sb + ps * STG_SZ;
#pragma unroll
        for (int mt = 0; mt < 4; mt++) {
            CP_ASYNC16(st + mt * MAT_SZ + cr0 * LDA_S + cc0,
                       src[mt] + (size_t)cr0 * Dn + ps * 32 + (cc0 >> 1));
            CP_ASYNC16(st + mt * MAT_SZ + cr1 * LDA_S + cc0,
                       src[mt] + (size_t)cr1 * Dn + ps * 32 + (cc0 >> 1));
        }
        CP_COMMIT();
    }

#pragma unroll 1
    for (int s = 0; s < 32; s++) {
        CP_WAIT1();
        __syncthreads();

        const uint32_t stg = sb + (s % 3) * STG_SZ;
#pragma unroll
        for (int ks = 0; ks < 2; ks++) {
            uint32_t ah[2][4], al[2][4], bh[4][4], bl[4][4];
#pragma unroll
            for (int mf = 0; mf < 2; mf++) {
                const uint32_t ao = stg + (a_row + mf * 16) * LDA_S + ks * 32 + a_byt;
                ldsm_x4(ah[mf], ao);
                ldsm_x4(al[mf], ao + MAT_SZ);
            }
#pragma unroll
            for (int nq = 0; nq < 4; nq++) {
                const uint32_t bo = stg + 2 * MAT_SZ +
                                    (b_row + nq * 16) * LDA_S + ks * 32 + b_byt;
                ldsm_x4(bh[nq], bo);
                ldsm_x4(bl[nq], bo + MAT_SZ);
            }
#pragma unroll
            for (int mf = 0; mf < 2; mf++)
#pragma unroll
                for (int nq = 0; nq < 4; nq++) {
                    mma16816(acc[mf][nq * 2 + 0], ah[mf], bh[nq][0], bh[nq][1]);
                    mma16816(acc[mf][nq * 2 + 1], ah[mf], bh[nq][2], bh[nq][3]);
                    mma16816(acc[mf][nq * 2 + 0], ah[mf], bl[nq][0], bl[nq][1]);
                    mma16816(acc[mf][nq * 2 + 1], ah[mf], bl[nq][2], bl[nq][3]);
                    mma16816(acc[mf][nq * 2 + 0], al[mf], bh[nq][0], bh[nq][1]);
                    mma16816(acc[mf][nq * 2 + 1], al[mf], bh[nq][2], bh[nq][3]);
                }
        }

        if (s + 2 < 32) {
            const uint32_t st = sb + ((s + 2) % 3) * STG_SZ;
            const int k8 = (s + 2) * 32 + (cc0 >> 1);
#pragma unroll
            for (int mt = 0; mt < 4; mt++) {
                CP_ASYNC16(st + mt * MAT_SZ + cr0 * LDA_S + cc0,
                           src[mt] + (size_t)cr0 * Dn + k8);
                CP_ASYNC16(st + mt * MAT_SZ + cr1 * LDA_S + cc0,
                           src[mt] + (size_t)cr1 * Dn + k8);
            }
        }
        CP_COMMIT();
    }

#pragma unroll
    for (int mf = 0; mf < 2; mf++) {
        const int mr = m0 + wm * 32 + mf * 16 + (lane >> 2);
#pragma unroll
        for (int nf = 0; nf < 8; nf++) {
            const int c0 = n0 + wn * 64 + nf * 8 + (lane & 3) * 2;
            const float b0 = bias[c0], b1 = bias[c0 + 1];
#pragma unroll
            for (int rr = 0; rr < 2; rr++) {
                const int m = mr + rr * 8;
                float v0 = acc[mf][nf][rr * 2 + 0] + b0;
                float v1 = acc[mf][nf][rr * 2 + 1] + b1;
                if (MODE) {
                    v0 *= oscale; v1 *= oscale;
                    const int b = m >> 11, srow = m & (Sn - 1);
                    const int h = c0 >> 6, dk = c0 & 63;
                    const size_t idx =
                        (((size_t)(b * Hn + h)) * Sn + srow) * DKn + dk;
                    uint32_t hi, lo;
                    split2(v0, v1, hi, lo);
                    *(uint32_t*)(Yh + idx) = hi;
                    *(uint32_t*)(Yl + idx) = lo;
                } else {
                    float* dst = Yf + (size_t)m * Dn + c0;
                    dst[0] = v0; dst[1] = v1;
                }
            }
        }
    }
}

__global__ __launch_bounds__(256, 1) void gemm_proj(GemmJob a, GemmJob b, GemmJob c)
{
    extern __shared__ char sm[];
    GemmJob j = (blockIdx.z == 0) ? a : ((blockIdx.z == 1) ? b : c);
    gemm_body<1>(j.Xh, j.Xl, j.Wh, j.Wl, j.bias, nullptr, j.Yh, j.Yl,
                 j.oscale, sm);
}

__global__ __launch_bounds__(256, 1) void gemm_out(
    const __nv_bfloat16* Xh, const __nv_bfloat16* Xl,
    const __nv_bfloat16* Wh, const __nv_bfloat16* Wl,
    const float* bias, float* Yf)
{
    extern __shared__ char sm[];
    gemm_body<0>(Xh, Xl, Wh, Wl, bias, Yf, nullptr, nullptr, 1.0f, sm);
}

// ---------------------------------------------------------------------------
// HMMA causal flash attention, bf16 hi/lo inputs, cp.async double-buffered KV.
// 128 q-rows per CTA (8 warps x 16 rows), KV tiles of 64. Scores arrive in
// log2 domain (Q pre-scaled by 0.125*log2e), softmax uses fexp2.
// 2 CTAs/SM (regs capped at 128).
// ---------------------------------------------------------------------------
#define LDS_B   144
#define QMAT    18432                  // 128 * 144
#define KVMAT   9216                   // 64 * 144
#define KV_STG  (4 * KVMAT)            // 36864: Kh,Kl,Vh,Vl
#define ATTN_SMEM (2 * KV_STG)         // 73728

__global__ __launch_bounds__(256, 2) void attn_tc()
{
    extern __shared__ char smem[];
    const uint32_t sb = smem_u32(smem);
    const int tid = threadIdx.x, lane = tid & 31, wid = tid >> 5;

    const int qt = 15 - blockIdx.x;       // heavy blocks first
    const int bh = blockIdx.y;
    const int q0 = qt * 128;

    const size_t base = (size_t)bh * Sn * DKn;
    const __nv_bfloat16* Qh = g_Qh + base;
    const __nv_bfloat16* Ql = g_Ql + base;
    const __nv_bfloat16* Kh = g_Kh + base;
    const __nv_bfloat16* Kl = g_Kl + base;
    const __nv_bfloat16* Vh = g_Vh + base;
    const __nv_bfloat16* Vl = g_Vl + base;

    // ---- stage Q (bf16 hi/lo) into buf1, then pull into A-frags ----
    {
        char* qhd = smem + KV_STG;
        char* qld = smem + KV_STG + QMAT;
#pragma unroll
        for (int i = 0; i < 4; i++) {
            const int c = tid + i * 256;
            const int row = c >> 3, ch = c & 7;
            const uint32_t off = row * LDS_B + ch * 16;
            *(uint4*)(qhd + off) =
                *(const uint4*)(Qh + (size_t)(q0 + row) * DKn + ch * 8);
            *(uint4*)(qld + off) =
                *(const uint4*)(Ql + (size_t)(q0 + row) * DKn + ch * 8);
        }
    }
    __syncthreads();

    uint32_t qfh[4][4], qfl[4][4];
    {
        const uint32_t arow = wid * 16 + (lane & 15);
        const uint32_t abyt = (lane >> 4) * 16;
#pragma unroll
        for (int kc = 0; kc < 4; kc++) {
            const uint32_t ao = sb + KV_STG + arow * LDS_B + kc * 32 + abyt;
            ldsm_x4(qfh[kc], ao);
            ldsm_x4(qfl[kc], ao + QMAT);
        }
    }

    float accO[8][4];
#pragma unroll
    for (int j = 0; j < 8; j++)
#pragma unroll
        for (int k = 0; k < 4; k++) accO[j][k] = 0.f;
    float m_lo = -1e30f, m_hi = -1e30f, l_lo = 0.f, l_hi = 0.f;

    const int r_lo = q0 + wid * 16 + (lane >> 2);
    const int r_hi = r_lo + 8;
    const uint32_t brow = (lane & 7) + ((lane >> 4) << 3);
    const uint32_t bbyt = ((lane >> 3) & 1) * 16;
    const uint32_t vbyt = (lane >> 4) * 16;

    const int ntiles = 2 * qt + 2;

    // KV tile loader: 64 rows x 8 chunks (16B) per matrix; 2 rows per thread.
    const int lr = tid >> 3;              // 0..31
    const int lc = (tid & 7) * 16;        // byte offset within row
    const int le = lc >> 1;               // bf16 element offset

    {
        const uint32_t st = sb;
#pragma unroll
        for (int rr = 0; rr < 2; rr++) {
            const int row = lr + rr * 32;
            const uint32_t so = row * LDS_B + lc;
            const size_t go = (size_t)row * DKn + le;
            CP_ASYNC16(st + 0 * KVMAT + so, Kh + go);
            CP_ASYNC16(st + 1 * KVMAT + so, Kl + go);
            CP_ASYNC16(st + 2 * KVMAT + so, Vh + go);
            CP_ASYNC16(st + 3 * KVMAT + so, Vl + go);
        }
        CP_COMMIT();
    }

#pragma unroll 1
    for (int kt = 0; kt < ntiles; kt++) {
        CP_WAIT0();
        __syncthreads();

        if (kt + 1 < ntiles) {
            const uint32_t st = sb + ((kt + 1) & 1) * KV_STG;
#pragma unroll
            for (int rr = 0; rr < 2; rr++) {
                const int row = lr + rr * 32;
                const uint32_t so = row * LDS_B + lc;
                const size_t go = (size_t)((kt + 1) * 64 + row) * DKn + le;
                CP_ASYNC16(st + 0 * KVMAT + so, Kh + go);
                CP_ASYNC16(st + 1 * KVMAT + so, Kl + go);
                CP_ASYNC16(st + 2 * KVMAT + so, Vh + go);
                CP_ASYNC16(st + 3 * KVMAT + so, Vl + go);
            }
        }
        CP_COMMIT();

        const uint32_t stg = sb + (kt & 1) * KV_STG;
        const int k0 = kt * 64;

        // ---- S = Q K^T (3-term), log2-domain scores ----
        float s[8][4];
#pragma unroll
        for (int j = 0; j < 8; j++)
#pragma unroll
            for (int k = 0; k < 4; k++) s[j][k] = 0.f;

#pragma unroll
        for (int kc = 0; kc < 4; kc++) {
#pragma unroll
            for (int nq = 0; nq < 4; nq++) {
                const uint32_t bo = stg + (brow + nq * 16) * LDS_B + kc * 32 + bbyt;
                uint32_t kh[4], kl[4];
                ldsm_x4(kh, bo);
                ldsm_x4(kl, bo + KVMAT);
                mma16816(s[nq * 2 + 0], qfh[kc], kh[0], kh[1]);
                mma16816(s[nq * 2 + 1], qfh[kc], kh[2], kh[3]);
                mma16816(s[nq * 2 + 0], qfh[kc], kl[0], kl[1]);
                mma16816(s[nq * 2 + 1], qfh[kc], kl[2], kl[3]);
                mma16816(s[nq * 2 + 0], qfl[kc], kh[0], kh[1]);
                mma16816(s[nq * 2 + 1], qfl[kc], kh[2], kh[3]);
            }
        }

        // ---- causal mask (scale already folded into Q) ----
        if ((k0 + 63) > r_lo) {
#pragma unroll
            for (int j = 0; j < 8; j++) {
                const int c = k0 + j * 8 + (lane & 3) * 2;
                if (c > r_lo)     s[j][0] = -1e30f;
                if (c + 1 > r_lo) s[j][1] = -1e30f;
                if (c > r_hi)     s[j][2] = -1e30f;
                if (c + 1 > r_hi) s[j][3] = -1e30f;
            }
        }

        // ---- online softmax (base-2) ----
        float mx0 = -1e30f, mx1 = -1e30f;
#pragma unroll
        for (int j = 0; j < 8; j++) {
            mx0 = fmaxf(mx0, fmaxf(s[j][0], s[j][1]));
            mx1 = fmaxf(mx1, fmaxf(s[j][2], s[j][3]));
        }
        mx0 = fmaxf(mx0, __shfl_xor_sync(0xffffffffu, mx0, 1));
        mx0 = fmaxf(mx0, __shfl_xor_sync(0xffffffffu, mx0, 2));
        mx1 = fmaxf(mx1, __shfl_xor_sync(0xffffffffu, mx1, 1));
        mx1 = fmaxf(mx1, __shfl_xor_sync(0xffffffffu, mx1, 2));
        const float mn0 = fmaxf(m_lo, mx0);
        const float mn1 = fmaxf(m_hi, mx1);
        const float a0 = fexp2(m_lo - mn0);
        const float a1 = fexp2(m_hi - mn1);
        m_lo = mn0; m_hi = mn1;

        float sum0 = 0.f, sum1 = 0.f;
#pragma unroll
        for (int j = 0; j < 8; j++) {
            s[j][0] = fexp2(s[j][0] - mn0);
            s[j][1] = fexp2(s[j][1] - mn0);
            s[j][2] = fexp2(s[j][2] - mn1);
            s[j][3] = fexp2(s[j][3] - mn1);
            sum0 += s[j][0] + s[j][1];
            sum1 += s[j][2] + s[j][3];
        }
        sum0 += __shfl_xor_sync(0xffffffffu, sum0, 1);
        sum0 += __shfl_xor_sync(0xffffffffu, sum0, 2);
        sum1 += __shfl_xor_sync(0xffffffffu, sum1, 1);
        sum1 += __shfl_xor_sync(0xffffffffu, sum1, 2);
        l_lo = l_lo * a0 + sum0;
        l_hi = l_hi * a1 + sum1;
#pragma unroll
        for (int j = 0; j < 8; j++) {
            accO[j][0] *= a0; accO[j][1] *= a0;
            accO[j][2] *= a1; accO[j][3] *= a1;
        }

        // ---- O += P V (3-term) ----
#pragma unroll
        for (int kc = 0; kc < 4; kc++) {
            uint32_t ph[4], pl[4];
            {
                const float p00 = s[2 * kc][0],     p01 = s[2 * kc][1];
                const float p02 = s[2 * kc][2],     p03 = s[2 * kc][3];
                const float p10 = s[2 * kc + 1][0], p11 = s[2 * kc + 1][1];
                const float p12 = s[2 * kc + 1][2], p13 = s[2 * kc + 1][3];
                ph[0] = packbf(p00, p01);
                ph[1] = packbf(p02, p03);
                ph[2] = packbf(p10, p11);
                ph[3] = packbf(p12, p13);
                pl[0] = packbf(p00 - __bfloat162float(__float2bfloat16_rn(p00)),
                               p01 - __bfloat162float(__float2bfloat16_rn(p01)));
                pl[1] = packbf(p02 - __bfloat162float(__float2bfloat16_rn(p02)),
                               p03 - __bfloat162float(__float2bfloat16_rn(p03)));
                pl[2] = packbf(p10 - __bfloat162float(__float2bfloat16_rn(p10)),
                               p11 - __bfloat162float(__float2bfloat16_rn(p11)));
                pl[3] = packbf(p12 - __bfloat162float(__float2bfloat16_rn(p12)),
                               p13 - __bfloat162float(__float2bfloat16_rn(p13)));
            }
            const uint32_t vrow = kc * 16 + (lane & 15);
#pragma unroll
            for (int np = 0; np < 4; np++) {
                const uint32_t vo = stg + 2 * KVMAT + vrow * LDS_B + np * 32 + vbyt;
                uint32_t vh[4], vl[4];
                ldsm_x4_t(vh, vo);
                ldsm_x4_t(vl, vo + KVMAT);
                mma16816(accO[np * 2 + 0], ph, vh[0], vh[1]);
                mma16816(accO[np * 2 + 1], ph, vh[2], vh[3]);
                mma16816(accO[np * 2 + 0], ph, vl[0], vl[1]);
                mma16816(accO[np * 2 + 1], ph, vl[2], vl[3]);
                mma16816(accO[np * 2 + 0], pl, vh[0], vh[1]);
                mma16816(accO[np * 2 + 1], pl, vh[2], vh[3]);
            }
        }
    }

    // ---- epilogue: normalize, split to bf16 hi/lo, write [B,S,D] ----
    const float il0 = 1.0f / l_lo;
    const float il1 = 1.0f / l_hi;
    const int b = bh >> 4, h = bh & 15;
    const int c_base = h * DKn + (lane & 3) * 2;
#pragma unroll
    for (int j = 0; j < 8; j++) {
        const int c = c_base + j * 8;
        const size_t i0 = ((size_t)(b * Sn + r_lo)) * Dn + c;
        const size_t i1 = ((size_t)(b * Sn + r_hi)) * Dn + c;
        uint32_t hi, lo;
        split2(accO[j][0] * il0, accO[j][1] * il0, hi, lo);
        *(uint32_t*)(g_Ah + i0) = hi;
        *(uint32_t*)(g_Al + i0) = lo;
        split2(accO[j][2] * il1, accO[j][3] * il1, hi, lo);
        *(uint32_t*)(g_Ah + i1) = hi;
        *(uint32_t*)(g_Al + i1) = lo;
    }
}

// ---------------------------------------------------------------------------
extern "C" void kernel_launch(void* const* d_in, const int* in_sizes, int n_in,
                              void* d_out, int out_size)
{
    const float* k_in = (const float*)d_in[0];
    const float* q_in = (const float*)d_in[1];
    const float* v_in = (const float*)d_in[2];
    const float* w_q  = (const float*)d_in[3];
    const float* b_q  = (const float*)d_in[4];
    const float* w_k  = (const float*)d_in[5];
    const float* b_k  = (const float*)d_in[6];
    const float* w_v  = (const float*)d_in[7];
    const float* b_v  = (const float*)d_in[8];
    const float* w_o  = (const float*)d_in[9];
    const float* b_o  = (const float*)d_in[10];
    float* out = (float*)d_out;

    __nv_bfloat16 *xqh, *xql, *xkh, *xkl, *xvh, *xvl;
    __nv_bfloat16 *wqh, *wql, *wkh, *wkl, *wvh, *wvl, *woh, *wol;
    __nv_bfloat16 *Qh, *Ql, *Kh, *Kl, *Vh, *Vl, *Ah, *Al;
    cudaGetSymbolAddress((void**)&xqh, g_xqh); cudaGetSymbolAddress((void**)&xql, g_xql);
    cudaGetSymbolAddress((void**)&xkh, g_xkh); cudaGetSymbolAddress((void**)&xkl, g_xkl);
    cudaGetSymbolAddress((void**)&xvh, g_xvh); cudaGetSymbolAddress((void**)&xvl, g_xvl);
    cudaGetSymbolAddress((void**)&wqh, g_wqh); cudaGetSymbolAddress((void**)&wql, g_wql);
    cudaGetSymbolAddress((void**)&wkh, g_wkh); cudaGetSymbolAddress((void**)&wkl, g_wkl);
    cudaGetSymbolAddress((void**)&wvh, g_wvh); cudaGetSymbolAddress((void**)&wvl, g_wvl);
    cudaGetSymbolAddress((void**)&woh, g_woh); cudaGetSymbolAddress((void**)&wol, g_wol);
    cudaGetSymbolAddress((void**)&Qh, g_Qh);   cudaGetSymbolAddress((void**)&Ql, g_Ql);
    cudaGetSymbolAddress((void**)&Kh, g_Kh);   cudaGetSymbolAddress((void**)&Kl, g_Kl);
    cudaGetSymbolAddress((void**)&Vh, g_Vh);   cudaGetSymbolAddress((void**)&Vl, g_Vl);
    cudaGetSymbolAddress((void**)&Ah, g_Ah);   cudaGetSymbolAddress((void**)&Al, g_Al);

    cudaFuncSetAttribute(gemm_proj, cudaFuncAttributeMaxDynamicSharedMemorySize,
                         GEMM_SMEM);
    cudaFuncSetAttribute(gemm_out, cudaFuncAttributeMaxDynamicSharedMemorySize,
                         GEMM_SMEM);
    cudaFuncSetAttribute(attn_tc, cudaFuncAttributeMaxDynamicSharedMemorySize,
                         ATTN_SMEM);

    // one-launch conversion prepass
    conv_all<<<dim3(1024, 7), 256>>>(
        q_in, k_in, v_in, w_q, w_k, w_v, w_o,
        xqh, xql, xkh, xkl, xvh, xvl,
        wqh, wql, wkh, wkl, wvh, wvl, woh, wol);

    // merged Q/K/V projection GEMMs (Q output pre-scaled by 0.125*log2e)
    GemmJob jq = { xqh, xql, wqh, wql, b_q, Qh, Ql, 0.125f * 1.4426950408889634f };
    GemmJob jk = { xkh, xkl, wkh, wkl, b_k, Kh, Kl, 1.0f };
    GemmJob jv = { xvh, xvl, wvh, wvl, b_v, Vh, Vl, 1.0f };
    gemm_proj<<<dim3(32, 8, 3), 256, GEMM_SMEM>>>(jq, jk, jv);

    attn_tc<<<dim3(16, 32), 256, ATTN_SMEM>>>();

    gemm_out<<<dim3(32, 8), 256, GEMM_SMEM>>>(Ah, Al, woh, wol, b_o, out);
}

// round 9
// speedup vs baseline: 3.1910x; 1.0290x over previous
#include <cuda_runtime.h>
#include <cuda_bf16.h>
#include <cstdint>

#define Bn 2
#define Sn 2048
#define Dn 1024
#define Hn 16
#define DKn 64

#define NELEM (4096 * 1024)
#define WELEM (1024 * 1024)

// bf16 hi/lo scratch (device globals; no allocations allowed)
__device__ __nv_bfloat16 g_xqh[NELEM], g_xql[NELEM];
__device__ __nv_bfloat16 g_xkh[NELEM], g_xkl[NELEM];
__device__ __nv_bfloat16 g_xvh[NELEM], g_xvl[NELEM];
__device__ __nv_bfloat16 g_wqh[WELEM], g_wql[WELEM];
__device__ __nv_bfloat16 g_wkh[WELEM], g_wkl[WELEM];
__device__ __nv_bfloat16 g_wvh[WELEM], g_wvl[WELEM];
__device__ __nv_bfloat16 g_woh[WELEM], g_wol[WELEM];
__device__ __nv_bfloat16 g_Qh[NELEM], g_Ql[NELEM];   // [B,H,S,DK] (pre-scaled)
__device__ __nv_bfloat16 g_Kh[NELEM], g_Kl[NELEM];
__device__ __nv_bfloat16 g_Vh[NELEM], g_Vl[NELEM];
__device__ __nv_bfloat16 g_Ah[NELEM], g_Al[NELEM];   // [B,S,D]

// ---------------------------------------------------------------------------
// Helpers
// ---------------------------------------------------------------------------
__device__ __forceinline__ uint32_t smem_u32(const void* p) {
    uint32_t a;
    asm("{ .reg .u64 t; cvta.to.shared.u64 t, %1; cvt.u32.u64 %0, t; }"
        : "=r"(a) : "l"(p));
    return a;
}

__device__ __forceinline__ void ldsm_x4(uint32_t (&r)[4], uint32_t addr) {
    asm volatile("ldmatrix.sync.aligned.m8n8.x4.shared.b16 {%0,%1,%2,%3}, [%4];"
        : "=r"(r[0]), "=r"(r[1]), "=r"(r[2]), "=r"(r[3]) : "r"(addr));
}

__device__ __forceinline__ void ldsm_x4_t(uint32_t (&r)[4], uint32_t addr) {
    asm volatile("ldmatrix.sync.aligned.m8n8.x4.trans.shared.b16 {%0,%1,%2,%3}, [%4];"
        : "=r"(r[0]), "=r"(r[1]), "=r"(r[2]), "=r"(r[3]) : "r"(addr));
}

__device__ __forceinline__ void mma16816(float (&d)[4], const uint32_t (&a)[4],
                                         uint32_t b0, uint32_t b1) {
    asm volatile(
        "mma.sync.aligned.m16n8k16.row.col.f32.bf16.bf16.f32 "
        "{%0,%1,%2,%3}, {%4,%5,%6,%7}, {%8,%9}, {%0,%1,%2,%3};"
        : "+f"(d[0]), "+f"(d[1]), "+f"(d[2]), "+f"(d[3])
        : "r"(a[0]), "r"(a[1]), "r"(a[2]), "r"(a[3]), "r"(b0), "r"(b1));
}

#define CP_ASYNC16(dst, src) \
    asm volatile("cp.async.cg.shared.global [%0], [%1], 16;" \
                 :: "r"(dst), "l"(src) : "memory")
#define CP_COMMIT()  asm volatile("cp.async.commit_group;" ::: "memory")
#define CP_WAIT0()   asm volatile("cp.async.wait_group 0;" ::: "memory")
#define CP_WAIT1()   asm volatile("cp.async.wait_group 1;" ::: "memory")

__device__ __forceinline__ void split4(float4 v, uint2& hi, uint2& lo) {
    __nv_bfloat16 h0 = __float2bfloat16_rn(v.x);
    __nv_bfloat16 h1 = __float2bfloat16_rn(v.y);
    __nv_bfloat16 h2 = __float2bfloat16_rn(v.z);
    __nv_bfloat16 h3 = __float2bfloat16_rn(v.w);
    __nv_bfloat16 l0 = __float2bfloat16_rn(v.x - __bfloat162float(h0));
    __nv_bfloat16 l1 = __float2bfloat16_rn(v.y - __bfloat162float(h1));
    __nv_bfloat16 l2 = __float2bfloat16_rn(v.z - __bfloat162float(h2));
    __nv_bfloat16 l3 = __float2bfloat16_rn(v.w - __bfloat162float(h3));
    hi.x = ((uint32_t)__bfloat16_as_ushort(h1) << 16) | __bfloat16_as_ushort(h0);
    hi.y = ((uint32_t)__bfloat16_as_ushort(h3) << 16) | __bfloat16_as_ushort(h2);
    lo.x = ((uint32_t)__bfloat16_as_ushort(l1) << 16) | __bfloat16_as_ushort(l0);
    lo.y = ((uint32_t)__bfloat16_as_ushort(l3) << 16) | __bfloat16_as_ushort(l2);
}

__device__ __forceinline__ void split2(float a, float b, uint32_t& hi, uint32_t& lo) {
    __nv_bfloat16 ha = __float2bfloat16_rn(a);
    __nv_bfloat16 hb = __float2bfloat16_rn(b);
    __nv_bfloat16 la = __float2bfloat16_rn(a - __bfloat162float(ha));
    __nv_bfloat16 lb = __float2bfloat16_rn(b - __bfloat162float(hb));
    hi = ((uint32_t)__bfloat16_as_ushort(hb) << 16) | __bfloat16_as_ushort(ha);
    lo = ((uint32_t)__bfloat16_as_ushort(lb) << 16) | __bfloat16_as_ushort(la);
}

__device__ __forceinline__ uint32_t packbf(float a, float b) {
    return ((uint32_t)__bfloat16_as_ushort(__float2bfloat16_rn(b)) << 16) |
           __bfloat16_as_ushort(__float2bfloat16_rn(a));
}

// Fast 2^x on the FMA pipe. Valid for x <= 0 (clamped at -126). |err|~2.4e-6.
__device__ __forceinline__ float fexp2(float x) {
    x = fmaxf(x, -126.0f);
    float n = rintf(x);
    float r = x - n;                       // exact, r in [-0.5, 0.5]
    float p = fmaf(r, 1.3333558e-3f, 9.6181291e-3f);
    p = fmaf(r, p, 5.5504109e-2f);
    p = fmaf(r, p, 2.4022651e-1f);
    p = fmaf(r, p, 6.9314718e-1f);
    p = fmaf(r, p, 1.0f);
    int e = ((int)n + 127) << 23;
    return p * __int_as_float(e);
}

// ---------------------------------------------------------------------------
// Prepass: fp32 -> bf16 hi/lo split for all 7 tensors in ONE launch.
// ---------------------------------------------------------------------------
__global__ __launch_bounds__(256) void conv_all(
    const float* __restrict__ q, const float* __restrict__ k,
    const float* __restrict__ v,
    const float* __restrict__ wq, const float* __restrict__ wk,
    const float* __restrict__ wv, const float* __restrict__ wo,
    __nv_bfloat16* qh, __nv_bfloat16* ql,
    __nv_bfloat16* kh, __nv_bfloat16* kl,
    __nv_bfloat16* vh, __nv_bfloat16* vl,
    __nv_bfloat16* wqh, __nv_bfloat16* wql,
    __nv_bfloat16* wkh, __nv_bfloat16* wkl,
    __nv_bfloat16* wvh, __nv_bfloat16* wvl,
    __nv_bfloat16* woh, __nv_bfloat16* wol)
{
    const int z = blockIdx.y;
    const float* src;
    __nv_bfloat16 *H, *L;
    int n4;
    switch (z) {
        case 0: src = q;  H = qh;  L = ql;  n4 = NELEM / 4; break;
        case 1: src = k;  H = kh;  L = kl;  n4 = NELEM / 4; break;
        case 2: src = v;  H = vh;  L = vl;  n4 = NELEM / 4; break;
        case 3: src = wq; H = wqh; L = wql; n4 = WELEM / 4; break;
        case 4: src = wk; H = wkh; L = wkl; n4 = WELEM / 4; break;
        case 5: src = wv; H = wvh; L = wvl; n4 = WELEM / 4; break;
        default: src = wo; H = woh; L = wol; n4 = WELEM / 4; break;
    }
    const int base = blockIdx.x * 1024 + threadIdx.x;
    if (base >= n4) return;
#pragma unroll
    for (int u = 0; u < 4; u++) {
        const int i = base + u * 256;
        if (i < n4) {
            float4 vv = ((const float4*)src)[i];
            uint2 h, l;
            split4(vv, h, l);
            ((uint2*)H)[i] = h;
            ((uint2*)L)[i] = l;
        }
    }
}

// ---------------------------------------------------------------------------
// bf16 HMMA GEMM body, 3-term split, cp.async 2-stage pipeline, 2 CTAs/SM.
// Tile 128x128, BK=32, 256 threads, 8 warps 4(M)x2(N).
// ---------------------------------------------------------------------------
#define LDA_S   80
#define MAT_SZ  (128 * LDA_S)            // 10240
#define STG_SZ  (4 * MAT_SZ)             // 40960
#define GEMM_SMEM (2 * STG_SZ)           // 81920

struct GemmJob {
    const __nv_bfloat16 *Xh, *Xl, *Wh, *Wl;
    const float* bias;
    __nv_bfloat16 *Yh, *Yl;
    float oscale;
};

template <int MODE>
__device__ __forceinline__ void gemm_body(
    const __nv_bfloat16* __restrict__ Xh, const __nv_bfloat16* __restrict__ Xl,
    const __nv_bfloat16* __restrict__ Wh, const __nv_bfloat16* __restrict__ Wl,
    const float* __restrict__ bias,
    float* __restrict__ Yf,
    __nv_bfloat16* __restrict__ Yh, __nv_bfloat16* __restrict__ Yl,
    float oscale, char* sm)
{
    const uint32_t sb = smem_u32(sm);
    const int tid  = threadIdx.x;
    const int lane = tid & 31;
    const int wid  = tid >> 5;
    const int wm   = wid >> 1;
    const int wn   = wid & 1;

    const int m0 = blockIdx.x * 128;
    const int n0 = blockIdx.y * 128;
    const __nv_bfloat16* src[4] = {
        Xh + (size_t)m0 * Dn, Xl + (size_t)m0 * Dn,
        Wh + (size_t)n0 * Dn, Wl + (size_t)n0 * Dn };

    const int cr0 = (tid + 0)   >> 2;
    const int cc0 = (tid & 3)   * 16;
    const int cr1 = (tid + 256) >> 2;

    const uint32_t a_row = wm * 32 + (lane & 15);
    const uint32_t a_byt = (lane >> 4) * 16;
    const uint32_t b_row = wn * 64 + (lane & 7) + ((lane >> 4) << 3);
    const uint32_t b_byt = ((lane >> 3) & 1) * 16;

    float acc[2][8][4];
#pragma unroll
    for (int i = 0; i < 2; i++)
#pragma unroll
        for (int j = 0; j < 8; j++)
#pragma unroll
            for (int k = 0; k < 4; k++) acc[i][j][k] = 0.f;

    // prologue: stages 0,1
#pragma unroll
    for (int ps = 0; ps < 2; ps++) {
        const uint32_t st = sb + ps * STG_SZ;
#pragma unroll
        for (int mt = 0; mt < 4; mt++) {
            CP_ASYNC16(st + mt * MAT_SZ + cr0 * LDA_S + cc0,
                       src[mt] + (size_t)cr0 * Dn + ps * 32 + (cc0 >> 1));
            CP_ASYNC16(st + mt * MAT_SZ + cr1 * LDA_S + cc0,
                       src[mt] + (size_t)cr1 * Dn + ps * 32 + (cc0 >> 1));
        }
        CP_COMMIT();
    }

#pragma unroll 1
    for (int s = 0; s < 32; s++) {
        CP_WAIT1();               // stage s resident (s+1 may be in flight)
        __syncthreads();

        const uint32_t stg = sb + (s & 1) * STG_SZ;
#pragma unroll
        for (int ks = 0; ks < 2; ks++) {
            uint32_t ah[2][4], al[2][4];
#pragma unroll
            for (int mf = 0; mf < 2; mf++) {
                const uint32_t ao = stg + (a_row + mf * 16) * LDA_S + ks * 32 + a_byt;
                ldsm_x4(ah[mf], ao);
                ldsm_x4(al[mf], ao + MAT_SZ);
            }
#pragma unroll
            for (int nq = 0; nq < 4; nq++) {
                const uint32_t bo = stg + 2 * MAT_SZ +
                                    (b_row + nq * 16) * LDA_S + ks * 32 + b_byt;
                uint32_t bh[4], bl[4];
                ldsm_x4(bh, bo);
                ldsm_x4(bl, bo + MAT_SZ);
#pragma unroll
                for (int mf = 0; mf < 2; mf++) {
                    mma16816(acc[mf][nq * 2 + 0], ah[mf], bh[0], bh[1]);
                    mma16816(acc[mf][nq * 2 + 1], ah[mf], bh[2], bh[3]);
                    mma16816(acc[mf][nq * 2 + 0], ah[mf], bl[0], bl[1]);
                    mma16816(acc[mf][nq * 2 + 1], ah[mf], bl[2], bl[3]);
                    mma16816(acc[mf][nq * 2 + 0], al[mf], bh[0], bh[1]);
                    mma16816(acc[mf][nq * 2 + 1], al[mf], bh[2], bh[3]);
                }
            }
        }

        __syncthreads();          // all warps done reading buf s&1
        if (s + 2 < 32) {
            const uint32_t st = sb + (s & 1) * STG_SZ;   // reuse just-freed buf
            const int k8 = (s + 2) * 32 + (cc0 >> 1);
#pragma unroll
            for (int mt = 0; mt < 4; mt++) {
                CP_ASYNC16(st + mt * MAT_SZ + cr0 * LDA_S + cc0,
                           src[mt] + (size_t)cr0 * Dn + k8);
                CP_ASYNC16(st + mt * MAT_SZ + cr1 * LDA_S + cc0,
                           src[mt] + (size_t)cr1 * Dn + k8);
            }
        }
        CP_COMMIT();
    }

#pragma unroll
    for (int mf = 0; mf < 2; mf++) {
        const int mr = m0 + wm * 32 + mf * 16 + (lane >> 2);
#pragma unroll
        for (int nf = 0; nf < 8; nf++) {
            const int c0 = n0 + wn * 64 + nf * 8 + (lane & 3) * 2;
            const float b0 = bias[c0], b1 = bias[c0 + 1];
#pragma unroll
            for (int rr = 0; rr < 2; rr++) {
                const int m = mr + rr * 8;
                float v0 = acc[mf][nf][rr * 2 + 0] + b0;
                float v1 = acc[mf][nf][rr * 2 + 1] + b1;
                if (MODE) {
                    v0 *= oscale; v1 *= oscale;
                    const int b = m >> 11, srow = m & (Sn - 1);
                    const int h = c0 >> 6, dk = c0 & 63;
                    const size_t idx =
                        (((size_t)(b * Hn + h)) * Sn + srow) * DKn + dk;
                    uint32_t hi, lo;
                    split2(v0, v1, hi, lo);
                    *(uint32_t*)(Yh + idx) = hi;
                    *(uint32_t*)(Yl + idx) = lo;
                } else {
                    float* dst = Yf + (size_t)m * Dn + c0;
                    dst[0] = v0; dst[1] = v1;
                }
            }
        }
    }
}

__global__ __launch_bounds__(256, 2) void gemm_proj(GemmJob a, GemmJob b, GemmJob c)
{
    extern __shared__ char sm[];
    GemmJob j = (blockIdx.z == 0) ? a : ((blockIdx.z == 1) ? b : c);
    gemm_body<1>(j.Xh, j.Xl, j.Wh, j.Wl, j.bias, nullptr, j.Yh, j.Yl,
                 j.oscale, sm);
}

__global__ __launch_bounds__(256, 2) void gemm_out(
    const __nv_bfloat16* Xh, const __nv_bfloat16* Xl,
    const __nv_bfloat16* Wh, const __nv_bfloat16* Wl,
    const float* bias, float* Yf)
{
    extern __shared__ char sm[];
    gemm_body<0>(Xh, Xl, Wh, Wl, bias, Yf, nullptr, nullptr, 1.0f, sm);
}

// ---------------------------------------------------------------------------
// HMMA causal flash attention (unchanged from round 8: 2 CTAs/SM, fexp2,
// cp.async double-buffered KV, Q pre-scaled into log2 domain).
// ---------------------------------------------------------------------------
#define LDS_B   144
#define QMAT    18432                  // 128 * 144
#define KVMAT   9216                   // 64 * 144
#define KV_STG  (4 * KVMAT)            // 36864: Kh,Kl,Vh,Vl
#define ATTN_SMEM (2 * KV_STG)         // 73728

__global__ __launch_bounds__(256, 2) void attn_tc()
{
    extern __shared__ char smem[];
    const uint32_t sb = smem_u32(smem);
    const int tid = threadIdx.x, lane = tid & 31, wid = tid >> 5;

    const int qt = 15 - blockIdx.x;       // heavy blocks first
    const int bh = blockIdx.y;
    const int q0 = qt * 128;

    const size_t base = (size_t)bh * Sn * DKn;
    const __nv_bfloat16* Qh = g_Qh + base;
    const __nv_bfloat16* Ql = g_Ql + base;
    const __nv_bfloat16* Kh = g_Kh + base;
    const __nv_bfloat16* Kl = g_Kl + base;
    const __nv_bfloat16* Vh = g_Vh + base;
    const __nv_bfloat16* Vl = g_Vl + base;

    // ---- stage Q (bf16 hi/lo) into buf1, then pull into A-frags ----
    {
        char* qhd = smem + KV_STG;
        char* qld = smem + KV_STG + QMAT;
#pragma unroll
        for (int i = 0; i < 4; i++) {
            const int c = tid + i * 256;
            const int row = c >> 3, ch = c & 7;
            const uint32_t off = row * LDS_B + ch * 16;
            *(uint4*)(qhd + off) =
                *(const uint4*)(Qh + (size_t)(q0 + row) * DKn + ch * 8);
            *(uint4*)(qld + off) =
                *(const uint4*)(Ql + (size_t)(q0 + row) * DKn + ch * 8);
        }
    }
    __syncthreads();

    uint32_t qfh[4][4], qfl[4][4];
    {
        const uint32_t arow = wid * 16 + (lane & 15);
        const uint32_t abyt = (lane >> 4) * 16;
#pragma unroll
        for (int kc = 0; kc < 4; kc++) {
            const uint32_t ao = sb + KV_STG + arow * LDS_B + kc * 32 + abyt;
            ldsm_x4(qfh[kc], ao);
            ldsm_x4(qfl[kc], ao + QMAT);
        }
    }

    float accO[8][4];
#pragma unroll
    for (int j = 0; j < 8; j++)
#pragma unroll
        for (int k = 0; k < 4; k++) accO[j][k] = 0.f;
    float m_lo = -1e30f, m_hi = -1e30f, l_lo = 0.f, l_hi = 0.f;

    const int r_lo = q0 + wid * 16 + (lane >> 2);
    const int r_hi = r_lo + 8;
    const uint32_t brow = (lane & 7) + ((lane >> 4) << 3);
    const uint32_t bbyt = ((lane >> 3) & 1) * 16;
    const uint32_t vbyt = (lane >> 4) * 16;

    const int ntiles = 2 * qt + 2;

    const int lr = tid >> 3;              // 0..31
    const int lc = (tid & 7) * 16;        // byte offset within row
    const int le = lc >> 1;               // bf16 element offset

    {
        const uint32_t st = sb;
#pragma unroll
        for (int rr = 0; rr < 2; rr++) {
            const int row = lr + rr * 32;
            const uint32_t so = row * LDS_B + lc;
            const size_t go = (size_t)row * DKn + le;
            CP_ASYNC16(st + 0 * KVMAT + so, Kh + go);
            CP_ASYNC16(st + 1 * KVMAT + so, Kl + go);
            CP_ASYNC16(st + 2 * KVMAT + so, Vh + go);
            CP_ASYNC16(st + 3 * KVMAT + so, Vl + go);
        }
        CP_COMMIT();
    }

#pragma unroll 1
    for (int kt = 0; kt < ntiles; kt++) {
        CP_WAIT0();
        __syncthreads();

        if (kt + 1 < ntiles) {
            const uint32_t st = sb + ((kt + 1) & 1) * KV_STG;
#pragma unroll
            for (int rr = 0; rr < 2; rr++) {
                const int row = lr + rr * 32;
                const uint32_t so = row * LDS_B + lc;
                const size_t go = (size_t)((kt + 1) * 64 + row) * DKn + le;
                CP_ASYNC16(st + 0 * KVMAT + so, Kh + go);
                CP_ASYNC16(st + 1 * KVMAT + so, Kl + go);
                CP_ASYNC16(st + 2 * KVMAT + so, Vh + go);
                CP_ASYNC16(st + 3 * KVMAT + so, Vl + go);
            }
        }
        CP_COMMIT();

        const uint32_t stg = sb + (kt & 1) * KV_STG;
        const int k0 = kt * 64;

        // ---- S = Q K^T (3-term), log2-domain scores ----
        float s[8][4];
#pragma unroll
        for (int j = 0; j < 8; j++)
#pragma unroll
            for (int k = 0; k < 4; k++) s[j][k] = 0.f;

#pragma unroll
        for (int kc = 0; kc < 4; kc++) {
#pragma unroll
            for (int nq = 0; nq < 4; nq++) {
                const uint32_t bo = stg + (brow + nq * 16) * LDS_B + kc * 32 + bbyt;
                uint32_t kh[4], kl[4];
                ldsm_x4(kh, bo);
                ldsm_x4(kl, bo + KVMAT);
                mma16816(s[nq * 2 + 0], qfh[kc], kh[0], kh[1]);
                mma16816(s[nq * 2 + 1], qfh[kc], kh[2], kh[3]);
                mma16816(s[nq * 2 + 0], qfh[kc], kl[0], kl[1]);
                mma16816(s[nq * 2 + 1], qfh[kc], kl[2], kl[3]);
                mma16816(s[nq * 2 + 0], qfl[kc], kh[0], kh[1]);
                mma16816(s[nq * 2 + 1], qfl[kc], kh[2], kh[3]);
            }
        }

        // ---- causal mask (scale already folded into Q) ----
        if ((k0 + 63) > r_lo) {
#pragma unroll
            for (int j = 0; j < 8; j++) {
                const int c = k0 + j * 8 + (lane & 3) * 2;
                if (c > r_lo)     s[j][0] = -1e30f;
                if (c + 1 > r_lo) s[j][1] = -1e30f;
                if (c > r_hi)     s[j][2] = -1e30f;
                if (c + 1 > r_hi) s[j][3] = -1e30f;
            }
        }

        // ---- online softmax (base-2) ----
        float mx0 = -1e30f, mx1 = -1e30f;
#pragma unroll
        for (int j = 0; j < 8; j++) {
            mx0 = fmaxf(mx0, fmaxf(s[j][0], s[j][1]));
            mx1 = fmaxf(mx1, fmaxf(s[j][2], s[j][3]));
        }
        mx0 = fmaxf(mx0, __shfl_xor_sync(0xffffffffu, mx0, 1));
        mx0 = fmaxf(mx0, __shfl_xor_sync(0xffffffffu, mx0, 2));
        mx1 = fmaxf(mx1, __shfl_xor_sync(0xffffffffu, mx1, 1));
        mx1 = fmaxf(mx1, __shfl_xor_sync(0xffffffffu, mx1, 2));
        const float mn0 = fmaxf(m_lo, mx0);
        const float mn1 = fmaxf(m_hi, mx1);
        const float a0 = fexp2(m_lo - mn0);
        const float a1 = fexp2(m_hi - mn1);
        m_lo = mn0; m_hi = mn1;

        float sum0 = 0.f, sum1 = 0.f;
#pragma unroll
        for (int j = 0; j < 8; j++) {
            s[j][0] = fexp2(s[j][0] - mn0);
            s[j][1] = fexp2(s[j][1] - mn0);
            s[j][2] = fexp2(s[j][2] - mn1);
            s[j][3] = fexp2(s[j][3] - mn1);
            sum0 += s[j][0] + s[j][1];
            sum1 += s[j][2] + s[j][3];
        }
        sum0 += __shfl_xor_sync(0xffffffffu, sum0, 1);
        sum0 += __shfl_xor_sync(0xffffffffu, sum0, 2);
        sum1 += __shfl_xor_sync(0xffffffffu, sum1, 1);
        sum1 += __shfl_xor_sync(0xffffffffu, sum1, 2);
        l_lo = l_lo * a0 + sum0;
        l_hi = l_hi * a1 + sum1;
#pragma unroll
        for (int j = 0; j < 8; j++) {
            accO[j][0] *= a0; accO[j][1] *= a0;
            accO[j][2] *= a1; accO[j][3] *= a1;
        }

        // ---- O += P V (3-term) ----
#pragma unroll
        for (int kc = 0; kc < 4; kc++) {
            uint32_t ph[4], pl[4];
            {
                const float p00 = s[2 * kc][0],     p01 = s[2 * kc][1];
                const float p02 = s[2 * kc][2],     p03 = s[2 * kc][3];
                const float p10 = s[2 * kc + 1][0], p11 = s[2 * kc + 1][1];
                const float p12 = s[2 * kc + 1][2], p13 = s[2 * kc + 1][3];
                ph[0] = packbf(p00, p01);
                ph[1] = packbf(p02, p03);
                ph[2] = packbf(p10, p11);
                ph[3] = packbf(p12, p13);
                pl[0] = packbf(p00 - __bfloat162float(__float2bfloat16_rn(p00)),
                               p01 - __bfloat162float(__float2bfloat16_rn(p01)));
                pl[1] = packbf(p02 - __bfloat162float(__float2bfloat16_rn(p02)),
                               p03 - __bfloat162float(__float2bfloat16_rn(p03)));
                pl[2] = packbf(p10 - __bfloat162float(__float2bfloat16_rn(p10)),
                               p11 - __bfloat162float(__float2bfloat16_rn(p11)));
                pl[3] = packbf(p12 - __bfloat162float(__float2bfloat16_rn(p12)),
                               p13 - __bfloat162float(__float2bfloat16_rn(p13)));
            }
            const uint32_t vrow = kc * 16 + (lane & 15);
#pragma unroll
            for (int np = 0; np < 4; np++) {
                const uint32_t vo = stg + 2 * KVMAT + vrow * LDS_B + np * 32 + vbyt;
                uint32_t vh[4], vl[4];
                ldsm_x4_t(vh, vo);
                ldsm_x4_t(vl, vo + KVMAT);
                mma16816(accO[np * 2 + 0], ph, vh[0], vh[1]);
                mma16816(accO[np * 2 + 1], ph, vh[2], vh[3]);
                mma16816(accO[np * 2 + 0], ph, vl[0], vl[1]);
                mma16816(accO[np * 2 + 1], ph, vl[2], vl[3]);
                mma16816(accO[np * 2 + 0], pl, vh[0], vh[1]);
                mma16816(accO[np * 2 + 1], pl, vh[2], vh[3]);
            }
        }
    }

    // ---- epilogue: normalize, split to bf16 hi/lo, write [B,S,D] ----
    const float il0 = 1.0f / l_lo;
    const float il1 = 1.0f / l_hi;
    const int b = bh >> 4, h = bh & 15;
    const int c_base = h * DKn + (lane & 3) * 2;
#pragma unroll
    for (int j = 0; j < 8; j++) {
        const int c = c_base + j * 8;
        const size_t i0 = ((size_t)(b * Sn + r_lo)) * Dn + c;
        const size_t i1 = ((size_t)(b * Sn + r_hi)) * Dn + c;
        uint32_t hi, lo;
        split2(accO[j][0] * il0, accO[j][1] * il0, hi, lo);
        *(uint32_t*)(g_Ah + i0) = hi;
        *(uint32_t*)(g_Al + i0) = lo;
        split2(accO[j][2] * il1, accO[j][3] * il1, hi, lo);
        *(uint32_t*)(g_Ah + i1) = hi;
        *(uint32_t*)(g_Al + i1) = lo;
    }
}

// ---------------------------------------------------------------------------
extern "C" void kernel_launch(void* const* d_in, const int* in_sizes, int n_in,
                              void* d_out, int out_size)
{
    const float* k_in = (const float*)d_in[0];
    const float* q_in = (const float*)d_in[1];
    const float* v_in = (const float*)d_in[2];
    const float* w_q  = (const float*)d_in[3];
    const float* b_q  = (const float*)d_in[4];
    const float* w_k  = (const float*)d_in[5];
    const float* b_k  = (const float*)d_in[6];
    const float* w_v  = (const float*)d_in[7];
    const float* b_v  = (const float*)d_in[8];
    const float* w_o  = (const float*)d_in[9];
    const float* b_o  = (const float*)d_in[10];
    float* out = (float*)d_out;

    __nv_bfloat16 *xqh, *xql, *xkh, *xkl, *xvh, *xvl;
    __nv_bfloat16 *wqh, *wql, *wkh, *wkl, *wvh, *wvl, *woh, *wol;
    __nv_bfloat16 *Qh, *Ql, *Kh, *Kl, *Vh, *Vl, *Ah, *Al;
    cudaGetSymbolAddress((void**)&xqh, g_xqh); cudaGetSymbolAddress((void**)&xql, g_xql);
    cudaGetSymbolAddress((void**)&xkh, g_xkh); cudaGetSymbolAddress((void**)&xkl, g_xkl);
    cudaGetSymbolAddress((void**)&xvh, g_xvh); cudaGetSymbolAddress((void**)&xvl, g_xvl);
    cudaGetSymbolAddress((void**)&wqh, g_wqh); cudaGetSymbolAddress((void**)&wql, g_wql);
    cudaGetSymbolAddress((void**)&wkh, g_wkh); cudaGetSymbolAddress((void**)&wkl, g_wkl);
    cudaGetSymbolAddress((void**)&wvh, g_wvh); cudaGetSymbolAddress((void**)&wvl, g_wvl);
    cudaGetSymbolAddress((void**)&woh, g_woh); cudaGetSymbolAddress((void**)&wol, g_wol);
    cudaGetSymbolAddress((void**)&Qh, g_Qh);   cudaGetSymbolAddress((void**)&Ql, g_Ql);
    cudaGetSymbolAddress((void**)&Kh, g_Kh);   cudaGetSymbolAddress((void**)&Kl, g_Kl);
    cudaGetSymbolAddress((void**)&Vh, g_Vh);   cudaGetSymbolAddress((void**)&Vl, g_Vl);
    cudaGetSymbolAddress((void**)&Ah, g_Ah);   cudaGetSymbolAddress((void**)&Al, g_Al);

    cudaFuncSetAttribute(gemm_proj, cudaFuncAttributeMaxDynamicSharedMemorySize,
                         GEMM_SMEM);
    cudaFuncSetAttribute(gemm_out, cudaFuncAttributeMaxDynamicSharedMemorySize,
                         GEMM_SMEM);
    cudaFuncSetAttribute(attn_tc, cudaFuncAttributeMaxDynamicSharedMemorySize,
                         ATTN_SMEM);

    // one-launch conversion prepass
    conv_all<<<dim3(1024, 7), 256>>>(
        q_in, k_in, v_in, w_q, w_k, w_v, w_o,
        xqh, xql, xkh, xkl, xvh, xvl,
        wqh, wql, wkh, wkl, wvh, wvl, woh, wol);

    // merged Q/K/V projection GEMMs (Q output pre-scaled by 0.125*log2e)
    GemmJob jq = { xqh, xql, wqh, wql, b_q, Qh, Ql, 0.125f * 1.4426950408889634f };
    GemmJob jk = { xkh, xkl, wkh, wkl, b_k, Kh, Kl, 1.0f };
    GemmJob jv = { xvh, xvl, wvh, wvl, b_v, Vh, Vl, 1.0f };
    gemm_proj<<<dim3(32, 8, 3), 256, GEMM_SMEM>>>(jq, jk, jv);

    attn_tc<<<dim3(16, 32), 256, ATTN_SMEM>>>();

    gemm_out<<<dim3(32, 8), 256, GEMM_SMEM>>>(Ah, Al, woh, wol, b_o, out);
}